// round 11
// baseline (speedup 1.0000x reference)
#include <cuda_runtime.h>
#include <cuda_bf16.h>
#include <cuda_fp16.h>
#include <math.h>
#include <float.h>
#include <stdint.h>

// Problem dims (fixed by the dataset)
#define B_ROWS 2048
#define N_KEYS 50000
#define D_DIM  256
#define V_DIM  256
#define TOPK   8
#define NCAND  16
#define N_PAD  50048   // 391 * 128
#define N_TCH  6256    // chunk (8-col) maxes per row; ids >= 6250 poisoned -inf
#define NG8    782     // N_TCH / 8 uint4 groups
#define MAXCH  192     // per-row collected-chunk cap

// ---------------------------------------------------------------------------
// Scratch (static __device__ arrays; allocation is banned)
// ---------------------------------------------------------------------------
__device__ float          g_q[B_ROWS * D_DIM];               // q_norm
__device__ float          g_kn[(size_t)N_KEYS * D_DIM];      // k_norm
__device__ __nv_bfloat16  g_ah[(size_t)B_ROWS * D_DIM];      // bf16(q_norm)
__device__ __nv_bfloat16  g_bh[(size_t)N_PAD * D_DIM];       // bf16(k_norm), pad rows zero
__device__ __half         g_tmax[(size_t)B_ROWS * N_TCH];    // chunk maxes (~26 MB)
__device__ int            g_topi[B_ROWS * TOPK];

// ---------------------------------------------------------------------------
// cp.async helpers
// ---------------------------------------------------------------------------
__device__ __forceinline__ uint32_t smem_u32(const void* p)
{
    uint32_t a;
    asm("{ .reg .u64 t; cvta.to.shared.u64 t, %1; cvt.u32.u64 %0, t; }" : "=r"(a) : "l"(p));
    return a;
}
__device__ __forceinline__ void cp_async16(uint32_t s, const void* g)
{
    asm volatile("cp.async.cg.shared.global [%0], [%1], 16;" :: "r"(s), "l"(g));
}
#define CP_COMMIT() asm volatile("cp.async.commit_group;")
#define CP_WAIT(n)  asm volatile("cp.async.wait_group %0;" :: "n"(n))

// ---------------------------------------------------------------------------
// bf16 mma.sync GEMM -> per-8-col chunk maxes ONLY (no sim matrix).
// CTA tile 128x128, 512 threads, 16 warps (4x4), warp tile 32x32, BK=32.
// ---------------------------------------------------------------------------
#define KST 40

__global__ void __launch_bounds__(512) simtc_kernel(
    const __nv_bfloat16* __restrict__ Ah,
    const __nv_bfloat16* __restrict__ Bh,
    __half* __restrict__ tmax)
{
    __shared__ __align__(16) uint16_t As[2][128][KST];
    __shared__ __align__(16) uint16_t Bs[2][128][KST];
    __shared__ __align__(16) __half   tmx_s[128][16];

    const int tid  = threadIdx.x;
    const int wid  = tid >> 5;
    const int lane = tid & 31;
    const int gid  = lane >> 2;        // 0..7
    const int q2   = (lane & 3) * 2;   // 0,2,4,6
    const int wm   = (wid >> 2) * 32;
    const int wn   = (wid & 3) * 32;
    const int m0   = blockIdx.y * 128;
    const int n0   = blockIdx.x * 128;

    const uint32_t sA = smem_u32(As);
    const uint32_t sB = smem_u32(Bs);
    const int lrow = tid >> 2;
    const int lcu  = tid & 3;

    float c[2][4][4];
#pragma unroll
    for (int i = 0; i < 2; ++i)
#pragma unroll
        for (int j = 0; j < 4; ++j)
#pragma unroll
            for (int v = 0; v < 4; ++v) c[i][j][v] = 0.f;

    auto load_chunk = [&](int buf, int kc) {
        uint32_t so = (uint32_t)(((buf * 128 + lrow) * KST + lcu * 8) * 2);
        cp_async16(sA + so, Ah + (size_t)(m0 + lrow) * D_DIM + kc * 32 + lcu * 8);
        cp_async16(sB + so, Bh + (size_t)(n0 + lrow) * D_DIM + kc * 32 + lcu * 8);
    };

    auto compute_chunk = [&](int buf) {
#pragma unroll
        for (int ks = 0; ks < 2; ++ks) {
            const int k0 = ks * 16;
            uint32_t a[2][4];
#pragma unroll
            for (int mt = 0; mt < 2; ++mt) {
                int r0 = wm + mt * 16 + gid;
                a[mt][0] = *(const uint32_t*)&As[buf][r0    ][k0 + q2];
                a[mt][1] = *(const uint32_t*)&As[buf][r0 + 8][k0 + q2];
                a[mt][2] = *(const uint32_t*)&As[buf][r0    ][k0 + q2 + 8];
                a[mt][3] = *(const uint32_t*)&As[buf][r0 + 8][k0 + q2 + 8];
            }
            uint32_t b[4][2];
#pragma unroll
            for (int nt = 0; nt < 4; ++nt) {
                int n = wn + nt * 8 + gid;
                b[nt][0] = *(const uint32_t*)&Bs[buf][n][k0 + q2];
                b[nt][1] = *(const uint32_t*)&Bs[buf][n][k0 + q2 + 8];
            }
#pragma unroll
            for (int mt = 0; mt < 2; ++mt)
#pragma unroll
                for (int nt = 0; nt < 4; ++nt)
                    asm volatile(
                        "mma.sync.aligned.m16n8k16.row.col.f32.bf16.bf16.f32 "
                        "{%0,%1,%2,%3}, {%4,%5,%6,%7}, {%8,%9}, {%0,%1,%2,%3};"
                        : "+f"(c[mt][nt][0]), "+f"(c[mt][nt][1]),
                          "+f"(c[mt][nt][2]), "+f"(c[mt][nt][3])
                        : "r"(a[mt][0]), "r"(a[mt][1]), "r"(a[mt][2]), "r"(a[mt][3]),
                          "r"(b[nt][0]), "r"(b[nt][1]));
        }
    };

    load_chunk(0, 0); CP_COMMIT();
    load_chunk(1, 1); CP_COMMIT();

    const int nchunk = D_DIM / 32;     // 8
#pragma unroll
    for (int t = 0; t < nchunk; ++t) {
        if (t == nchunk - 1) { CP_WAIT(0); } else { CP_WAIT(1); }
        __syncthreads();
        compute_chunk(t & 1);
        __syncthreads();
        if (t + 2 < nchunk) { load_chunk(t & 1, t + 2); CP_COMMIT(); }
    }

    // Epilogue: per-(row, 8-col chunk) maxes via quad shuffles -> smem stage
    const __half NEGINF = __ushort_as_half((unsigned short)0xFC00);
#pragma unroll
    for (int mt = 0; mt < 2; ++mt) {
        int r = wm + mt * 16 + gid;
#pragma unroll
        for (int nt = 0; nt < 4; ++nt) {
            float mlo = fmaxf(c[mt][nt][0], c[mt][nt][1]);
            float mhi = fmaxf(c[mt][nt][2], c[mt][nt][3]);
            mlo = fmaxf(mlo, __shfl_xor_sync(0xffffffffu, mlo, 1));
            mlo = fmaxf(mlo, __shfl_xor_sync(0xffffffffu, mlo, 2));
            mhi = fmaxf(mhi, __shfl_xor_sync(0xffffffffu, mhi, 1));
            mhi = fmaxf(mhi, __shfl_xor_sync(0xffffffffu, mhi, 2));
            if ((lane & 3) == 0) {
                int  chc = (wn >> 3) + nt;                 // 0..15 within CTA
                bool pad = (n0 + wn + nt * 8) >= N_KEYS;   // chunk-aligned
                tmx_s[r][chc]     = pad ? NEGINF : __float2half_rn(mlo);
                tmx_s[r + 8][chc] = pad ? NEGINF : __float2half_rn(mhi);
            }
        }
    }
    __syncthreads();
    // Coalesced copy-out: 2048 halves = 512 x 8B
    {
        int row = tid >> 2, cq = tid & 3;
        uint2 v = *(const uint2*)&tmx_s[row][cq * 4];
        *(uint2*)(tmax + (size_t)(m0 + row) * N_TCH + (n0 >> 3) + cq * 4) = v;
    }
}

// ---------------------------------------------------------------------------
// fp32 NT SGEMM (small q = query @ W^T + b only)
// ---------------------------------------------------------------------------
#define BM 128
#define BN 128
#define BK 16

__global__ void __launch_bounds__(256) gemm_nt_kernel(
    const float* __restrict__ A, const float* __restrict__ B,
    float* __restrict__ C, const float* __restrict__ bias,
    int N, int K, int ldc)
{
    __shared__ __align__(16) float As[BK][BM];
    __shared__ __align__(16) float Bs[BK][BN];
    const int tid = threadIdx.x;
    const int tx  = tid & 15;
    const int ty  = tid >> 4;
    const int m0  = blockIdx.y * BM;
    const int n0  = blockIdx.x * BN;
    const int lr  = tid >> 2;
    const int lc  = (tid & 3) * 4;
    const float* Aptr = A + (size_t)m0 * K;
    const float* Bptr = B + (size_t)n0 * K;

    float acc[8][8];
#pragma unroll
    for (int i = 0; i < 8; ++i)
#pragma unroll
        for (int j = 0; j < 8; ++j) acc[i][j] = 0.f;

    for (int k0 = 0; k0 < K; k0 += BK) {
#pragma unroll
        for (int h = 0; h < 2; ++h) {
            int r = lr + h * 64;
            float4 v = *(const float4*)(Aptr + (size_t)r * K + k0 + lc);
            As[lc + 0][r] = v.x; As[lc + 1][r] = v.y;
            As[lc + 2][r] = v.z; As[lc + 3][r] = v.w;
            float4 w = *(const float4*)(Bptr + (size_t)r * K + k0 + lc);
            Bs[lc + 0][r] = w.x; Bs[lc + 1][r] = w.y;
            Bs[lc + 2][r] = w.z; Bs[lc + 3][r] = w.w;
        }
        __syncthreads();
#pragma unroll
        for (int kk = 0; kk < BK; ++kk) {
            float ra[8], rb[8];
            *(float4*)&ra[0] = *(const float4*)&As[kk][ty * 8];
            *(float4*)&ra[4] = *(const float4*)&As[kk][ty * 8 + 4];
            *(float4*)&rb[0] = *(const float4*)&Bs[kk][tx * 8];
            *(float4*)&rb[4] = *(const float4*)&Bs[kk][tx * 8 + 4];
#pragma unroll
            for (int i = 0; i < 8; ++i)
#pragma unroll
                for (int j = 0; j < 8; ++j)
                    acc[i][j] = fmaf(ra[i], rb[j], acc[i][j]);
        }
        __syncthreads();
    }
    float bi[8];
#pragma unroll
    for (int j = 0; j < 8; ++j) {
        int n = n0 + tx * 8 + j;
        bi[j] = bias ? ((n < N) ? bias[n] : 0.f) : 0.f;
    }
#pragma unroll
    for (int i = 0; i < 8; ++i) {
        int m = m0 + ty * 8 + i;
        float* crow = C + (size_t)m * ldc + n0 + tx * 8;
#pragma unroll
        for (int jv = 0; jv < 8; jv += 4) {
            float4 w;
            w.x = acc[i][jv + 0] + bi[jv + 0];
            w.y = acc[i][jv + 1] + bi[jv + 1];
            w.z = acc[i][jv + 2] + bi[jv + 2];
            w.w = acc[i][jv + 3] + bi[jv + 3];
            *(float4*)(crow + jv) = w;
        }
    }
}

// ---------------------------------------------------------------------------
// Row L2-normalize + fused bf16 cast. IEEE div/sqrt (matches reference).
// ---------------------------------------------------------------------------
__global__ void l2norm_rows_kernel(const float* __restrict__ src,
                                   float* __restrict__ dstf,
                                   __nv_bfloat16* __restrict__ dstb, int rows)
{
    int row  = blockIdx.x * 8 + (threadIdx.x >> 5);
    int lane = threadIdx.x & 31;
    if (row >= rows) return;
    const float4* p = (const float4*)(src + (size_t)row * D_DIM);
    float4 v0 = p[lane];
    float4 v1 = p[lane + 32];
    float ss = v0.x * v0.x + v0.y * v0.y + v0.z * v0.z + v0.w * v0.w
             + v1.x * v1.x + v1.y * v1.y + v1.z * v1.z + v1.w * v1.w;
#pragma unroll
    for (int off = 16; off > 0; off >>= 1)
        ss += __shfl_xor_sync(0xffffffffu, ss, off);
    float den = fmaxf(__fsqrt_rn(ss), 1e-12f);
    v0.x = __fdiv_rn(v0.x, den); v0.y = __fdiv_rn(v0.y, den);
    v0.z = __fdiv_rn(v0.z, den); v0.w = __fdiv_rn(v0.w, den);
    v1.x = __fdiv_rn(v1.x, den); v1.y = __fdiv_rn(v1.y, den);
    v1.z = __fdiv_rn(v1.z, den); v1.w = __fdiv_rn(v1.w, den);
    float4* q = (float4*)(dstf + (size_t)row * D_DIM);
    q[lane]      = v0;
    q[lane + 32] = v1;
    __nv_bfloat162* d2 = (__nv_bfloat162*)(dstb + (size_t)row * D_DIM);
    d2[lane * 2 + 0]        = __floats2bfloat162_rn(v0.x, v0.y);
    d2[lane * 2 + 1]        = __floats2bfloat162_rn(v0.z, v0.w);
    d2[(lane + 32) * 2 + 0] = __floats2bfloat162_rn(v1.x, v1.y);
    d2[(lane + 32) * 2 + 1] = __floats2bfloat162_rn(v1.z, v1.w);
}

// ---------------------------------------------------------------------------
// Fused candidate + exact rescore + top-8, one block (256 thr) per row.
// ---------------------------------------------------------------------------
__device__ __forceinline__ bool tk_better(float s1, int i1, float s2, int i2)
{
    return (s1 > s2) || (s1 == s2 && i1 < i2);
}

__device__ __forceinline__ float hmax8(uint4 pk)
{
    const __half2* h = (const __half2*)&pk;
    __half2 m01 = __hmax2(h[0], h[1]);
    __half2 m23 = __hmax2(h[2], h[3]);
    __half2 m   = __hmax2(m01, m23);
    return fmaxf(__low2float(m), __high2float(m));
}

__global__ void __launch_bounds__(256) candres_kernel(
    const __half* __restrict__ tmax, const float* __restrict__ q,
    const float* __restrict__ kn,
    float* __restrict__ out_scores, int* __restrict__ topi)
{
    __shared__ __align__(16) float qs[D_DIM];      // 16B-accessed: keep first+aligned
    __shared__ float thmax[256];
    __shared__ float sT;
    __shared__ int   scnt;
    __shared__ int   chid[MAXCH];
    __shared__ float cs[MAXCH * 8];
    __shared__ int   ci[MAXCH * 8];
    __shared__ float rs[256];
    __shared__ int   rk[256];
    __shared__ int   rp[256];

    const int r   = blockIdx.x;
    const int tid = threadIdx.x;
    const uint4* trow = (const uint4*)(tmax + (size_t)r * N_TCH);

    // q row to smem (float4 on 16B-aligned qs)
    if (tid < 64) ((float4*)qs)[tid] = ((const float4*)(q + (size_t)r * D_DIM))[tid];

    // Pass 1: per-thread slice max over chunk maxes
    float tm = -FLT_MAX;
    for (int g = tid; g < NG8; g += 256)
        tm = fmaxf(tm, hmax8(trow[g]));
    thmax[tid] = tm;
    if (tid == 0) scnt = 0;
    __syncthreads();

    // T = 16th largest of the 256 slice maxes (<= true 16th element value)
    if (tid < 32) {
        float l[8];
#pragma unroll
        for (int j = 0; j < 8; ++j) l[j] = thmax[tid * 8 + j];
        float T = -FLT_MAX;
        for (int it = 0; it < NCAND; ++it) {
            float lm = -FLT_MAX;
#pragma unroll
            for (int j = 0; j < 8; ++j) lm = fmaxf(lm, l[j]);
#pragma unroll
            for (int off = 16; off > 0; off >>= 1)
                lm = fmaxf(lm, __shfl_xor_sync(0xffffffffu, lm, off));
            bool done = false;
#pragma unroll
            for (int j = 0; j < 8; ++j)
                if (!done && l[j] == lm) { l[j] = -FLT_MAX; done = true; }
            T = lm;
        }
        if (tid == 0) sT = T;
    }
    __syncthreads();
    const float T = sT;

    // Pass 2: collect hot chunk ids (row cache-hot, ~25 hits)
    for (int g = tid; g < NG8; g += 256) {
        uint4 pk = trow[g];
        if (hmax8(pk) >= T) {
            const __half2* h = (const __half2*)&pk;
#pragma unroll
            for (int v = 0; v < 4; ++v) {
                float2 f = __half22float2(h[v]);
                if (f.x >= T) { int p = atomicAdd(&scnt, 1); if (p < MAXCH) chid[p] = g * 8 + v * 2; }
                if (f.y >= T) { int p = atomicAdd(&scnt, 1); if (p < MAXCH) chid[p] = g * 8 + v * 2 + 1; }
            }
        }
    }
    __syncthreads();
    const int CE = min(scnt, MAXCH) * 8;

    // Exact fp32 rescore of all elements in hot chunks (serial ascending-k
    // fma chain -- numerics identical to all prior passing rounds)
    for (int i = tid; i < CE; i += 256) {
        int n = chid[i >> 3] * 8 + (i & 7);
        const float* kr = kn + (size_t)n * D_DIM;
        float acc = 0.f;
#pragma unroll 8
        for (int k = 0; k < D_DIM; ++k)
            acc = fmaf(qs[k], kr[k], acc);
        cs[i] = acc; ci[i] = n;
    }
    __syncthreads();

    // Exact (score, index) top-8 selection
    for (int it = 0; it < TOPK; ++it) {
        float bs = -FLT_MAX; int bk = 0x7fffffff; int bp = -1;
        for (int i = tid; i < CE; i += 256)
            if (tk_better(cs[i], ci[i], bs, bk)) { bs = cs[i]; bk = ci[i]; bp = i; }
        rs[tid] = bs; rk[tid] = bk; rp[tid] = bp;
        __syncthreads();
        for (int off = 128; off > 0; off >>= 1) {
            if (tid < off) {
                if (tk_better(rs[tid + off], rk[tid + off], rs[tid], rk[tid])) {
                    rs[tid] = rs[tid + off]; rk[tid] = rk[tid + off]; rp[tid] = rp[tid + off];
                }
            }
            __syncthreads();
        }
        if (tid == 0) {
            out_scores[r * TOPK + it] = rs[0];
            topi[r * TOPK + it]       = rk[0];
            if (rp[0] >= 0) { cs[rp[0]] = -FLT_MAX; ci[rp[0]] = 0x7fffffff; }
        }
        __syncthreads();
    }
}

// ---------------------------------------------------------------------------
// usage passthrough + gather
// ---------------------------------------------------------------------------
__global__ void usage_init_kernel(const float* __restrict__ usage, float* __restrict__ out_usage)
{
    int i = blockIdx.x * blockDim.x + threadIdx.x;
    if (i < N_KEYS) out_usage[i] = usage[i];
}

__global__ void gather_kernel(const float* __restrict__ values, const int* __restrict__ topi,
                              float* __restrict__ out_rv, float* __restrict__ out_usage)
{
    int slot = blockIdx.x;
    int idx  = topi[slot];
    if (threadIdx.x == 0) atomicAdd(&out_usage[idx], 1.0f);
    const float4* src = (const float4*)(values + (size_t)idx * V_DIM);
    float4*       dst = (float4*)(out_rv + (size_t)slot * V_DIM);
    dst[threadIdx.x] = src[threadIdx.x];
}

// ---------------------------------------------------------------------------
// Launch
// ---------------------------------------------------------------------------
extern "C" void kernel_launch(void* const* d_in, const int* in_sizes, int n_in,
                              void* d_out, int out_size)
{
    const float* query  = (const float*)d_in[0];
    const float* W      = (const float*)d_in[1];
    const float* bias   = (const float*)d_in[2];
    const float* keys   = (const float*)d_in[3];
    const float* values = (const float*)d_in[4];
    const float* usage  = (const float*)d_in[5];

    float* out       = (float*)d_out;
    float* out_rv    = out;
    float* out_sc    = out + (size_t)B_ROWS * TOPK * V_DIM;
    float* out_usage = out_sc + (size_t)B_ROWS * TOPK;

    float*         q    = nullptr; cudaGetSymbolAddress((void**)&q,    g_q);
    float*         kn   = nullptr; cudaGetSymbolAddress((void**)&kn,   g_kn);
    __nv_bfloat16* ah   = nullptr; cudaGetSymbolAddress((void**)&ah,   g_ah);
    __nv_bfloat16* bh   = nullptr; cudaGetSymbolAddress((void**)&bh,   g_bh);
    __half*        tmx  = nullptr; cudaGetSymbolAddress((void**)&tmx,  g_tmax);
    int*           topi = nullptr; cudaGetSymbolAddress((void**)&topi, g_topi);

    // 1) q = query @ W^T + b
    gemm_nt_kernel<<<dim3(D_DIM / BN, B_ROWS / BM), 256>>>(
        query, W, q, bias, D_DIM, D_DIM, D_DIM);

    // 2) normalize + fused bf16 cast; zero bh pad rows
    l2norm_rows_kernel<<<B_ROWS / 8, 256>>>(q, q, ah, B_ROWS);
    l2norm_rows_kernel<<<(N_KEYS + 7) / 8, 256>>>(keys, kn, bh, N_KEYS);
    cudaMemsetAsync(bh + (size_t)N_KEYS * D_DIM, 0,
                    (size_t)(N_PAD - N_KEYS) * D_DIM * sizeof(__nv_bfloat16));

    // 3) bf16 tensor-core GEMM -> chunk maxes only (no sim matrix)
    simtc_kernel<<<dim3(N_PAD / 128, B_ROWS / 128), 512>>>(ah, bh, tmx);

    // 4) fused threshold + collect + exact rescore + top-8
    candres_kernel<<<B_ROWS, 256>>>(tmx, q, kn, out_sc, topi);

    // 5) usage + gather
    usage_init_kernel<<<(N_KEYS + 255) / 256, 256>>>(usage, out_usage);
    gather_kernel<<<B_ROWS * TOPK, 64>>>(values, topi, out_rv, out_usage);
}

// round 12
// speedup vs baseline: 1.3047x; 1.3047x over previous
#include <cuda_runtime.h>
#include <cuda_bf16.h>
#include <cuda_fp16.h>
#include <math.h>
#include <float.h>
#include <stdint.h>

// Problem dims (fixed by the dataset)
#define B_ROWS 2048
#define N_KEYS 50000
#define D_DIM  256
#define V_DIM  256
#define TOPK   8
#define NCAND  16
#define N_PAD  50048   // 391 * 128
#define N_TCH  6256    // chunk (8-col) maxes per row; ids >= 6250 poisoned -inf
#define NG8    782     // N_TCH / 8 uint4 groups
#define MAXCH  128     // per-row collected-chunk cap (expected ~25)

// ---------------------------------------------------------------------------
// Scratch (static __device__ arrays; allocation is banned)
// ---------------------------------------------------------------------------
__device__ float          g_q[B_ROWS * D_DIM];               // q_norm
__device__ float          g_kn[(size_t)N_KEYS * D_DIM];      // k_norm
__device__ __nv_bfloat16  g_ah[(size_t)B_ROWS * D_DIM];      // bf16(q_norm)
__device__ __nv_bfloat16  g_bh[(size_t)N_PAD * D_DIM];       // bf16(k_norm), pad rows zero
__device__ __half         g_tmax[(size_t)B_ROWS * N_TCH];    // chunk maxes (~26 MB)
__device__ int            g_topi[B_ROWS * TOPK];

// ---------------------------------------------------------------------------
// cp.async helpers
// ---------------------------------------------------------------------------
__device__ __forceinline__ uint32_t smem_u32(const void* p)
{
    uint32_t a;
    asm("{ .reg .u64 t; cvta.to.shared.u64 t, %1; cvt.u32.u64 %0, t; }" : "=r"(a) : "l"(p));
    return a;
}
__device__ __forceinline__ void cp_async16(uint32_t s, const void* g)
{
    asm volatile("cp.async.cg.shared.global [%0], [%1], 16;" :: "r"(s), "l"(g));
}
#define CP_COMMIT() asm volatile("cp.async.commit_group;")
#define CP_WAIT(n)  asm volatile("cp.async.wait_group %0;" :: "n"(n))

// ---------------------------------------------------------------------------
// bf16 mma.sync GEMM -> per-8-col chunk maxes ONLY (no sim matrix).
// CTA tile 128x128, 512 threads, 16 warps (4x4), warp tile 32x32, BK=32.
// ---------------------------------------------------------------------------
#define KST 40

__global__ void __launch_bounds__(512) simtc_kernel(
    const __nv_bfloat16* __restrict__ Ah,
    const __nv_bfloat16* __restrict__ Bh,
    __half* __restrict__ tmax)
{
    __shared__ __align__(16) uint16_t As[2][128][KST];
    __shared__ __align__(16) uint16_t Bs[2][128][KST];
    __shared__ __align__(16) __half   tmx_s[128][16];

    const int tid  = threadIdx.x;
    const int wid  = tid >> 5;
    const int lane = tid & 31;
    const int gid  = lane >> 2;        // 0..7
    const int q2   = (lane & 3) * 2;   // 0,2,4,6
    const int wm   = (wid >> 2) * 32;
    const int wn   = (wid & 3) * 32;
    const int m0   = blockIdx.y * 128;
    const int n0   = blockIdx.x * 128;

    const uint32_t sA = smem_u32(As);
    const uint32_t sB = smem_u32(Bs);
    const int lrow = tid >> 2;
    const int lcu  = tid & 3;

    float c[2][4][4];
#pragma unroll
    for (int i = 0; i < 2; ++i)
#pragma unroll
        for (int j = 0; j < 4; ++j)
#pragma unroll
            for (int v = 0; v < 4; ++v) c[i][j][v] = 0.f;

    auto load_chunk = [&](int buf, int kc) {
        uint32_t so = (uint32_t)(((buf * 128 + lrow) * KST + lcu * 8) * 2);
        cp_async16(sA + so, Ah + (size_t)(m0 + lrow) * D_DIM + kc * 32 + lcu * 8);
        cp_async16(sB + so, Bh + (size_t)(n0 + lrow) * D_DIM + kc * 32 + lcu * 8);
    };

    auto compute_chunk = [&](int buf) {
#pragma unroll
        for (int ks = 0; ks < 2; ++ks) {
            const int k0 = ks * 16;
            uint32_t a[2][4];
#pragma unroll
            for (int mt = 0; mt < 2; ++mt) {
                int r0 = wm + mt * 16 + gid;
                a[mt][0] = *(const uint32_t*)&As[buf][r0    ][k0 + q2];
                a[mt][1] = *(const uint32_t*)&As[buf][r0 + 8][k0 + q2];
                a[mt][2] = *(const uint32_t*)&As[buf][r0    ][k0 + q2 + 8];
                a[mt][3] = *(const uint32_t*)&As[buf][r0 + 8][k0 + q2 + 8];
            }
            uint32_t b[4][2];
#pragma unroll
            for (int nt = 0; nt < 4; ++nt) {
                int n = wn + nt * 8 + gid;
                b[nt][0] = *(const uint32_t*)&Bs[buf][n][k0 + q2];
                b[nt][1] = *(const uint32_t*)&Bs[buf][n][k0 + q2 + 8];
            }
#pragma unroll
            for (int mt = 0; mt < 2; ++mt)
#pragma unroll
                for (int nt = 0; nt < 4; ++nt)
                    asm volatile(
                        "mma.sync.aligned.m16n8k16.row.col.f32.bf16.bf16.f32 "
                        "{%0,%1,%2,%3}, {%4,%5,%6,%7}, {%8,%9}, {%0,%1,%2,%3};"
                        : "+f"(c[mt][nt][0]), "+f"(c[mt][nt][1]),
                          "+f"(c[mt][nt][2]), "+f"(c[mt][nt][3])
                        : "r"(a[mt][0]), "r"(a[mt][1]), "r"(a[mt][2]), "r"(a[mt][3]),
                          "r"(b[nt][0]), "r"(b[nt][1]));
        }
    };

    load_chunk(0, 0); CP_COMMIT();
    load_chunk(1, 1); CP_COMMIT();

    const int nchunk = D_DIM / 32;     // 8
#pragma unroll
    for (int t = 0; t < nchunk; ++t) {
        if (t == nchunk - 1) { CP_WAIT(0); } else { CP_WAIT(1); }
        __syncthreads();
        compute_chunk(t & 1);
        __syncthreads();
        if (t + 2 < nchunk) { load_chunk(t & 1, t + 2); CP_COMMIT(); }
    }

    // Epilogue: per-(row, 8-col chunk) maxes via quad shuffles -> smem stage
    const __half NEGINF = __ushort_as_half((unsigned short)0xFC00);
#pragma unroll
    for (int mt = 0; mt < 2; ++mt) {
        int r = wm + mt * 16 + gid;
#pragma unroll
        for (int nt = 0; nt < 4; ++nt) {
            float mlo = fmaxf(c[mt][nt][0], c[mt][nt][1]);
            float mhi = fmaxf(c[mt][nt][2], c[mt][nt][3]);
            mlo = fmaxf(mlo, __shfl_xor_sync(0xffffffffu, mlo, 1));
            mlo = fmaxf(mlo, __shfl_xor_sync(0xffffffffu, mlo, 2));
            mhi = fmaxf(mhi, __shfl_xor_sync(0xffffffffu, mhi, 1));
            mhi = fmaxf(mhi, __shfl_xor_sync(0xffffffffu, mhi, 2));
            if ((lane & 3) == 0) {
                int  chc = (wn >> 3) + nt;                 // 0..15 within CTA
                bool pad = (n0 + wn + nt * 8) >= N_KEYS;   // chunk-aligned
                tmx_s[r][chc]     = pad ? NEGINF : __float2half_rn(mlo);
                tmx_s[r + 8][chc] = pad ? NEGINF : __float2half_rn(mhi);
            }
        }
    }
    __syncthreads();
    // Coalesced copy-out: 2048 halves = 512 x 8B
    {
        int row = tid >> 2, cq = tid & 3;
        uint2 v = *(const uint2*)&tmx_s[row][cq * 4];
        *(uint2*)(tmax + (size_t)(m0 + row) * N_TCH + (n0 >> 3) + cq * 4) = v;
    }
}

// ---------------------------------------------------------------------------
// fp32 NT SGEMM (small q = query @ W^T + b only)
// ---------------------------------------------------------------------------
#define BM 128
#define BN 128
#define BK 16

__global__ void __launch_bounds__(256) gemm_nt_kernel(
    const float* __restrict__ A, const float* __restrict__ B,
    float* __restrict__ C, const float* __restrict__ bias,
    int N, int K, int ldc)
{
    __shared__ __align__(16) float As[BK][BM];
    __shared__ __align__(16) float Bs[BK][BN];
    const int tid = threadIdx.x;
    const int tx  = tid & 15;
    const int ty  = tid >> 4;
    const int m0  = blockIdx.y * BM;
    const int n0  = blockIdx.x * BN;
    const int lr  = tid >> 2;
    const int lc  = (tid & 3) * 4;
    const float* Aptr = A + (size_t)m0 * K;
    const float* Bptr = B + (size_t)n0 * K;

    float acc[8][8];
#pragma unroll
    for (int i = 0; i < 8; ++i)
#pragma unroll
        for (int j = 0; j < 8; ++j) acc[i][j] = 0.f;

    for (int k0 = 0; k0 < K; k0 += BK) {
#pragma unroll
        for (int h = 0; h < 2; ++h) {
            int r = lr + h * 64;
            float4 v = *(const float4*)(Aptr + (size_t)r * K + k0 + lc);
            As[lc + 0][r] = v.x; As[lc + 1][r] = v.y;
            As[lc + 2][r] = v.z; As[lc + 3][r] = v.w;
            float4 w = *(const float4*)(Bptr + (size_t)r * K + k0 + lc);
            Bs[lc + 0][r] = w.x; Bs[lc + 1][r] = w.y;
            Bs[lc + 2][r] = w.z; Bs[lc + 3][r] = w.w;
        }
        __syncthreads();
#pragma unroll
        for (int kk = 0; kk < BK; ++kk) {
            float ra[8], rb[8];
            *(float4*)&ra[0] = *(const float4*)&As[kk][ty * 8];
            *(float4*)&ra[4] = *(const float4*)&As[kk][ty * 8 + 4];
            *(float4*)&rb[0] = *(const float4*)&Bs[kk][tx * 8];
            *(float4*)&rb[4] = *(const float4*)&Bs[kk][tx * 8 + 4];
#pragma unroll
            for (int i = 0; i < 8; ++i)
#pragma unroll
                for (int j = 0; j < 8; ++j)
                    acc[i][j] = fmaf(ra[i], rb[j], acc[i][j]);
        }
        __syncthreads();
    }
    float bi[8];
#pragma unroll
    for (int j = 0; j < 8; ++j) {
        int n = n0 + tx * 8 + j;
        bi[j] = bias ? ((n < N) ? bias[n] : 0.f) : 0.f;
    }
#pragma unroll
    for (int i = 0; i < 8; ++i) {
        int m = m0 + ty * 8 + i;
        float* crow = C + (size_t)m * ldc + n0 + tx * 8;
#pragma unroll
        for (int jv = 0; jv < 8; jv += 4) {
            float4 w;
            w.x = acc[i][jv + 0] + bi[jv + 0];
            w.y = acc[i][jv + 1] + bi[jv + 1];
            w.z = acc[i][jv + 2] + bi[jv + 2];
            w.w = acc[i][jv + 3] + bi[jv + 3];
            *(float4*)(crow + jv) = w;
        }
    }
}

// ---------------------------------------------------------------------------
// Row L2-normalize + fused bf16 cast. IEEE div/sqrt (matches reference).
// ---------------------------------------------------------------------------
__global__ void l2norm_rows_kernel(const float* __restrict__ src,
                                   float* __restrict__ dstf,
                                   __nv_bfloat16* __restrict__ dstb, int rows)
{
    int row  = blockIdx.x * 8 + (threadIdx.x >> 5);
    int lane = threadIdx.x & 31;
    if (row >= rows) return;
    const float4* p = (const float4*)(src + (size_t)row * D_DIM);
    float4 v0 = p[lane];
    float4 v1 = p[lane + 32];
    float ss = v0.x * v0.x + v0.y * v0.y + v0.z * v0.z + v0.w * v0.w
             + v1.x * v1.x + v1.y * v1.y + v1.z * v1.z + v1.w * v1.w;
#pragma unroll
    for (int off = 16; off > 0; off >>= 1)
        ss += __shfl_xor_sync(0xffffffffu, ss, off);
    float den = fmaxf(__fsqrt_rn(ss), 1e-12f);
    v0.x = __fdiv_rn(v0.x, den); v0.y = __fdiv_rn(v0.y, den);
    v0.z = __fdiv_rn(v0.z, den); v0.w = __fdiv_rn(v0.w, den);
    v1.x = __fdiv_rn(v1.x, den); v1.y = __fdiv_rn(v1.y, den);
    v1.z = __fdiv_rn(v1.z, den); v1.w = __fdiv_rn(v1.w, den);
    float4* q = (float4*)(dstf + (size_t)row * D_DIM);
    q[lane]      = v0;
    q[lane + 32] = v1;
    __nv_bfloat162* d2 = (__nv_bfloat162*)(dstb + (size_t)row * D_DIM);
    d2[lane * 2 + 0]        = __floats2bfloat162_rn(v0.x, v0.y);
    d2[lane * 2 + 1]        = __floats2bfloat162_rn(v0.z, v0.w);
    d2[(lane + 32) * 2 + 0] = __floats2bfloat162_rn(v1.x, v1.y);
    d2[(lane + 32) * 2 + 1] = __floats2bfloat162_rn(v1.z, v1.w);
}

// ---------------------------------------------------------------------------
// Fused candidate + exact rescore + top-8, one block (256 thr) per row.
// Rescore is tiled: coalesced smem staging of candidate kn rows, then the
// bit-identical serial ascending-k fma chain from shared memory.
// ---------------------------------------------------------------------------
__device__ __forceinline__ bool tk_better(float s1, int i1, float s2, int i2)
{
    return (s1 > s2) || (s1 == s2 && i1 < i2);
}

__device__ __forceinline__ float hmax8(uint4 pk)
{
    const __half2* h = (const __half2*)&pk;
    __half2 m01 = __hmax2(h[0], h[1]);
    __half2 m23 = __hmax2(h[2], h[3]);
    __half2 m   = __hmax2(m01, m23);
    return fmaxf(__low2float(m), __high2float(m));
}

__global__ void __launch_bounds__(256) candres_kernel(
    const __half* __restrict__ tmax, const float* __restrict__ q,
    const float* __restrict__ kn,
    float* __restrict__ out_scores, int* __restrict__ topi)
{
    __shared__ __align__(16) float qs[D_DIM];
    __shared__ float st[32][257];          // staged kn rows (conflict-free stride)
    __shared__ float thmax[256];
    __shared__ float sT;
    __shared__ int   scnt;
    __shared__ int   chid[MAXCH];
    __shared__ float cs[MAXCH * 8];
    __shared__ int   ci[MAXCH * 8];
    __shared__ float rs[256];
    __shared__ int   rk[256];
    __shared__ int   rp[256];

    const int r   = blockIdx.x;
    const int tid = threadIdx.x;
    const uint4* trow = (const uint4*)(tmax + (size_t)r * N_TCH);

    // q row to smem
    if (tid < 64) ((float4*)qs)[tid] = ((const float4*)(q + (size_t)r * D_DIM))[tid];

    // Pass 1: per-thread slice max over chunk maxes
    float tm = -FLT_MAX;
    for (int g = tid; g < NG8; g += 256)
        tm = fmaxf(tm, hmax8(trow[g]));
    thmax[tid] = tm;
    if (tid == 0) scnt = 0;
    __syncthreads();

    // T = 16th largest of the 256 slice maxes (<= true 16th element value)
    if (tid < 32) {
        float l[8];
#pragma unroll
        for (int j = 0; j < 8; ++j) l[j] = thmax[tid * 8 + j];
        float T = -FLT_MAX;
        for (int it = 0; it < NCAND; ++it) {
            float lm = -FLT_MAX;
#pragma unroll
            for (int j = 0; j < 8; ++j) lm = fmaxf(lm, l[j]);
#pragma unroll
            for (int off = 16; off > 0; off >>= 1)
                lm = fmaxf(lm, __shfl_xor_sync(0xffffffffu, lm, off));
            bool done = false;
#pragma unroll
            for (int j = 0; j < 8; ++j)
                if (!done && l[j] == lm) { l[j] = -FLT_MAX; done = true; }
            T = lm;
        }
        if (tid == 0) sT = T;
    }
    __syncthreads();
    const float T = sT;

    // Pass 2: collect hot chunk ids (row cache-hot, ~25 hits)
    for (int g = tid; g < NG8; g += 256) {
        uint4 pk = trow[g];
        if (hmax8(pk) >= T) {
            const __half2* h = (const __half2*)&pk;
#pragma unroll
            for (int v = 0; v < 4; ++v) {
                float2 f = __half22float2(h[v]);
                if (f.x >= T) { int p = atomicAdd(&scnt, 1); if (p < MAXCH) chid[p] = g * 8 + v * 2; }
                if (f.y >= T) { int p = atomicAdd(&scnt, 1); if (p < MAXCH) chid[p] = g * 8 + v * 2 + 1; }
            }
        }
    }
    __syncthreads();
    const int CE = min(scnt, MAXCH) * 8;

    // Tiled exact rescore: stage 32 candidate rows coalesced, then serial
    // ascending-k fma chain from smem (identical numerics to prior rounds).
    for (int t0 = 0; t0 < CE; t0 += 32) {
        const int nr = min(32, CE - t0);
        // Stage (coalesced: warp covers 512B contiguous per instruction)
#pragma unroll
        for (int j = 0; j < 8; ++j) {
            int u  = j * 256 + tid;    // 0..2047
            int lr = u >> 6;           // staged row 0..31
            int lc = u & 63;           // float4 index within row
            if (lr < nr) {
                int e = t0 + lr;
                int n = chid[e >> 3] * 8 + (e & 7);
                float4 v = ((const float4*)(kn + (size_t)n * D_DIM))[lc];
                st[lr][lc * 4 + 0] = v.x; st[lr][lc * 4 + 1] = v.y;
                st[lr][lc * 4 + 2] = v.z; st[lr][lc * 4 + 3] = v.w;
            }
        }
        __syncthreads();
        if (tid < nr) {
            int e = t0 + tid;
            int n = chid[e >> 3] * 8 + (e & 7);
            float acc = 0.f;
#pragma unroll 8
            for (int k = 0; k < D_DIM; ++k)
                acc = fmaf(qs[k], st[tid][k], acc);
            cs[e] = acc; ci[e] = n;
        }
        __syncthreads();
    }

    // Exact (score, index) top-8 selection
    for (int it = 0; it < TOPK; ++it) {
        float bs = -FLT_MAX; int bk = 0x7fffffff; int bp = -1;
        for (int i = tid; i < CE; i += 256)
            if (tk_better(cs[i], ci[i], bs, bk)) { bs = cs[i]; bk = ci[i]; bp = i; }
        rs[tid] = bs; rk[tid] = bk; rp[tid] = bp;
        __syncthreads();
        for (int off = 128; off > 0; off >>= 1) {
            if (tid < off) {
                if (tk_better(rs[tid + off], rk[tid + off], rs[tid], rk[tid])) {
                    rs[tid] = rs[tid + off]; rk[tid] = rk[tid + off]; rp[tid] = rp[tid + off];
                }
            }
            __syncthreads();
        }
        if (tid == 0) {
            out_scores[r * TOPK + it] = rs[0];
            topi[r * TOPK + it]       = rk[0];
            if (rp[0] >= 0) { cs[rp[0]] = -FLT_MAX; ci[rp[0]] = 0x7fffffff; }
        }
        __syncthreads();
    }
}

// ---------------------------------------------------------------------------
// usage passthrough + gather
// ---------------------------------------------------------------------------
__global__ void usage_init_kernel(const float* __restrict__ usage, float* __restrict__ out_usage)
{
    int i = blockIdx.x * blockDim.x + threadIdx.x;
    if (i < N_KEYS) out_usage[i] = usage[i];
}

__global__ void gather_kernel(const float* __restrict__ values, const int* __restrict__ topi,
                              float* __restrict__ out_rv, float* __restrict__ out_usage)
{
    int slot = blockIdx.x;
    int idx  = topi[slot];
    if (threadIdx.x == 0) atomicAdd(&out_usage[idx], 1.0f);
    const float4* src = (const float4*)(values + (size_t)idx * V_DIM);
    float4*       dst = (float4*)(out_rv + (size_t)slot * V_DIM);
    dst[threadIdx.x] = src[threadIdx.x];
}

// ---------------------------------------------------------------------------
// Launch
// ---------------------------------------------------------------------------
extern "C" void kernel_launch(void* const* d_in, const int* in_sizes, int n_in,
                              void* d_out, int out_size)
{
    const float* query  = (const float*)d_in[0];
    const float* W      = (const float*)d_in[1];
    const float* bias   = (const float*)d_in[2];
    const float* keys   = (const float*)d_in[3];
    const float* values = (const float*)d_in[4];
    const float* usage  = (const float*)d_in[5];

    float* out       = (float*)d_out;
    float* out_rv    = out;
    float* out_sc    = out + (size_t)B_ROWS * TOPK * V_DIM;
    float* out_usage = out_sc + (size_t)B_ROWS * TOPK;

    float*         q    = nullptr; cudaGetSymbolAddress((void**)&q,    g_q);
    float*         kn   = nullptr; cudaGetSymbolAddress((void**)&kn,   g_kn);
    __nv_bfloat16* ah   = nullptr; cudaGetSymbolAddress((void**)&ah,   g_ah);
    __nv_bfloat16* bh   = nullptr; cudaGetSymbolAddress((void**)&bh,   g_bh);
    __half*        tmx  = nullptr; cudaGetSymbolAddress((void**)&tmx,  g_tmax);
    int*           topi = nullptr; cudaGetSymbolAddress((void**)&topi, g_topi);

    // 1) q = query @ W^T + b
    gemm_nt_kernel<<<dim3(D_DIM / BN, B_ROWS / BM), 256>>>(
        query, W, q, bias, D_DIM, D_DIM, D_DIM);

    // 2) normalize + fused bf16 cast; zero bh pad rows
    l2norm_rows_kernel<<<B_ROWS / 8, 256>>>(q, q, ah, B_ROWS);
    l2norm_rows_kernel<<<(N_KEYS + 7) / 8, 256>>>(keys, kn, bh, N_KEYS);
    cudaMemsetAsync(bh + (size_t)N_KEYS * D_DIM, 0,
                    (size_t)(N_PAD - N_KEYS) * D_DIM * sizeof(__nv_bfloat16));

    // 3) bf16 tensor-core GEMM -> chunk maxes only (no sim matrix)
    simtc_kernel<<<dim3(N_PAD / 128, B_ROWS / 128), 512>>>(ah, bh, tmx);

    // 4) fused threshold + collect + coalesced exact rescore + top-8
    candres_kernel<<<B_ROWS, 256>>>(tmx, q, kn, out_sc, topi);

    // 5) usage + gather
    usage_init_kernel<<<(N_KEYS + 255) / 256, 256>>>(usage, out_usage);
    gather_kernel<<<B_ROWS * TOPK, 64>>>(values, topi, out_rv, out_usage);
}

// round 14
// speedup vs baseline: 1.5096x; 1.1571x over previous
#include <cuda_runtime.h>
#include <cuda_bf16.h>
#include <cuda_fp16.h>
#include <math.h>
#include <float.h>
#include <stdint.h>

// Problem dims (fixed by the dataset)
#define B_ROWS 2048
#define N_KEYS 50000
#define D_DIM  256
#define V_DIM  256
#define TOPK   8
#define NCAND  16
#define N_PAD  50048   // 391 * 128
#define N_TCH  6256    // chunk (8-col) maxes per row; ids >= 6250 poisoned -inf
#define NG8    782     // N_TCH / 8 uint4 groups
#define MAXCH  128     // per-row collected-chunk cap (expected ~25)

// ---------------------------------------------------------------------------
// Scratch (static __device__ arrays; allocation is banned)
// ---------------------------------------------------------------------------
__device__ float          g_q[B_ROWS * D_DIM];               // q_norm
__device__ float          g_kn[(size_t)N_KEYS * D_DIM];      // k_norm
__device__ __nv_bfloat16  g_ah[(size_t)B_ROWS * D_DIM];      // bf16(q_norm)
__device__ __nv_bfloat16  g_bh[(size_t)N_PAD * D_DIM];       // bf16(k_norm), pad rows zero
__device__ __half         g_tmax[(size_t)B_ROWS * N_TCH];    // chunk maxes (~26 MB)
__device__ int            g_topi[B_ROWS * TOPK];

// ---------------------------------------------------------------------------
// smem/cp.async/ldmatrix helpers
// ---------------------------------------------------------------------------
__device__ __forceinline__ uint32_t smem_u32(const void* p)
{
    uint32_t a;
    asm("{ .reg .u64 t; cvta.to.shared.u64 t, %1; cvt.u32.u64 %0, t; }" : "=r"(a) : "l"(p));
    return a;
}
__device__ __forceinline__ void cp_async16(uint32_t s, const void* g)
{
    asm volatile("cp.async.cg.shared.global [%0], [%1], 16;" :: "r"(s), "l"(g));
}
#define CP_COMMIT() asm volatile("cp.async.commit_group;")
#define CP_WAIT(n)  asm volatile("cp.async.wait_group %0;" :: "n"(n))

__device__ __forceinline__ void ldsm_x4(uint32_t& r0, uint32_t& r1,
                                        uint32_t& r2, uint32_t& r3, uint32_t addr)
{
    asm volatile("ldmatrix.sync.aligned.m8n8.x4.shared.b16 {%0,%1,%2,%3}, [%4];"
                 : "=r"(r0), "=r"(r1), "=r"(r2), "=r"(r3) : "r"(addr));
}

// ---------------------------------------------------------------------------
// bf16 mma.sync GEMM -> per-8-col chunk maxes ONLY (no sim matrix).
// CTA tile 128x128, 512 threads, 16 warps (4x4), warp tile 32x32, BK=32.
// Fragment feed via ldmatrix.x4 (4 LDSM per K=16 step instead of 16 LDS).
// ---------------------------------------------------------------------------
#define KST 40

__global__ void __launch_bounds__(512) simtc_kernel(
    const __nv_bfloat16* __restrict__ Ah,
    const __nv_bfloat16* __restrict__ Bh,
    __half* __restrict__ tmax)
{
    __shared__ __align__(16) uint16_t As[2][128][KST];
    __shared__ __align__(16) uint16_t Bs[2][128][KST];
    __shared__ __align__(16) __half   tmx_s[128][16];

    const int tid  = threadIdx.x;
    const int wid  = tid >> 5;
    const int lane = tid & 31;
    const int wm   = (wid >> 2) * 32;
    const int wn   = (wid & 3) * 32;
    const int m0   = blockIdx.y * 128;
    const int n0   = blockIdx.x * 128;

    const uint32_t sA = smem_u32(As);
    const uint32_t sB = smem_u32(Bs);
    const int lrow = tid >> 2;
    const int lcu  = tid & 3;

    // ldmatrix lane address components (reproduce the scalar fragment
    // mapping bit-for-bit):
    const int aRow = lane & 15;             // A: matrix0/2 rows 0-7, 1/3 rows 8-15
    const int aKof = (lane >> 4) << 3;      // A: +8 k for matrices 2,3
    const int bIdx = lane >> 3;             // B: matrix id 0..3
    const int bRow = ((bIdx >> 1) << 3) + (lane & 7);  // nt-pair row
    const int bKof = (bIdx & 1) << 3;       // +8 k for odd matrices

    float c[2][4][4];
#pragma unroll
    for (int i = 0; i < 2; ++i)
#pragma unroll
        for (int j = 0; j < 4; ++j)
#pragma unroll
            for (int v = 0; v < 4; ++v) c[i][j][v] = 0.f;

    auto load_chunk = [&](int buf, int kc) {
        uint32_t so = (uint32_t)(((buf * 128 + lrow) * KST + lcu * 8) * 2);
        cp_async16(sA + so, Ah + (size_t)(m0 + lrow) * D_DIM + kc * 32 + lcu * 8);
        cp_async16(sB + so, Bh + (size_t)(n0 + lrow) * D_DIM + kc * 32 + lcu * 8);
    };

    auto compute_chunk = [&](int buf) {
#pragma unroll
        for (int ks = 0; ks < 2; ++ks) {
            const int k0 = ks * 16;
            uint32_t a[2][4];
#pragma unroll
            for (int mt = 0; mt < 2; ++mt) {
                uint32_t addr = sA + (uint32_t)(((buf * 128 + wm + mt * 16 + aRow) * KST
                                                 + k0 + aKof) * 2);
                ldsm_x4(a[mt][0], a[mt][1], a[mt][2], a[mt][3], addr);
            }
            uint32_t b[4][2];
#pragma unroll
            for (int np = 0; np < 2; ++np) {
                uint32_t addr = sB + (uint32_t)(((buf * 128 + wn + np * 16 + bRow) * KST
                                                 + k0 + bKof) * 2);
                uint32_t r0, r1, r2, r3;
                ldsm_x4(r0, r1, r2, r3, addr);
                b[np * 2][0] = r0; b[np * 2][1] = r1;
                b[np * 2 + 1][0] = r2; b[np * 2 + 1][1] = r3;
            }
#pragma unroll
            for (int mt = 0; mt < 2; ++mt)
#pragma unroll
                for (int nt = 0; nt < 4; ++nt)
                    asm volatile(
                        "mma.sync.aligned.m16n8k16.row.col.f32.bf16.bf16.f32 "
                        "{%0,%1,%2,%3}, {%4,%5,%6,%7}, {%8,%9}, {%0,%1,%2,%3};"
                        : "+f"(c[mt][nt][0]), "+f"(c[mt][nt][1]),
                          "+f"(c[mt][nt][2]), "+f"(c[mt][nt][3])
                        : "r"(a[mt][0]), "r"(a[mt][1]), "r"(a[mt][2]), "r"(a[mt][3]),
                          "r"(b[nt][0]), "r"(b[nt][1]));
        }
    };

    load_chunk(0, 0); CP_COMMIT();
    load_chunk(1, 1); CP_COMMIT();

    const int nchunk = D_DIM / 32;     // 8
#pragma unroll
    for (int t = 0; t < nchunk; ++t) {
        if (t == nchunk - 1) { CP_WAIT(0); } else { CP_WAIT(1); }
        __syncthreads();
        compute_chunk(t & 1);
        __syncthreads();
        if (t + 2 < nchunk) { load_chunk(t & 1, t + 2); CP_COMMIT(); }
    }

    // Epilogue: per-(row, 8-col chunk) maxes via quad shuffles -> smem stage
    const __half NEGINF = __ushort_as_half((unsigned short)0xFC00);
    const int gid = lane >> 2;
#pragma unroll
    for (int mt = 0; mt < 2; ++mt) {
        int r = wm + mt * 16 + gid;
#pragma unroll
        for (int nt = 0; nt < 4; ++nt) {
            float mlo = fmaxf(c[mt][nt][0], c[mt][nt][1]);
            float mhi = fmaxf(c[mt][nt][2], c[mt][nt][3]);
            mlo = fmaxf(mlo, __shfl_xor_sync(0xffffffffu, mlo, 1));
            mlo = fmaxf(mlo, __shfl_xor_sync(0xffffffffu, mlo, 2));
            mhi = fmaxf(mhi, __shfl_xor_sync(0xffffffffu, mhi, 1));
            mhi = fmaxf(mhi, __shfl_xor_sync(0xffffffffu, mhi, 2));
            if ((lane & 3) == 0) {
                int  chc = (wn >> 3) + nt;                 // 0..15 within CTA
                bool pad = (n0 + wn + nt * 8) >= N_KEYS;   // chunk-aligned
                tmx_s[r][chc]     = pad ? NEGINF : __float2half_rn(mlo);
                tmx_s[r + 8][chc] = pad ? NEGINF : __float2half_rn(mhi);
            }
        }
    }
    __syncthreads();
    // Coalesced copy-out: 2048 halves = 512 x 8B
    {
        int row = tid >> 2, cq = tid & 3;
        uint2 v = *(const uint2*)&tmx_s[row][cq * 4];
        *(uint2*)(tmax + (size_t)(m0 + row) * N_TCH + (n0 >> 3) + cq * 4) = v;
    }
}

// ---------------------------------------------------------------------------
// fp32 NT SGEMM (small q = query @ W^T + b only)
// ---------------------------------------------------------------------------
#define BM 128
#define BN 128
#define BK 16

__global__ void __launch_bounds__(256) gemm_nt_kernel(
    const float* __restrict__ A, const float* __restrict__ B,
    float* __restrict__ C, const float* __restrict__ bias,
    int N, int K, int ldc)
{
    __shared__ __align__(16) float As[BK][BM];
    __shared__ __align__(16) float Bs[BK][BN];
    const int tid = threadIdx.x;
    const int tx  = tid & 15;
    const int ty  = tid >> 4;
    const int m0  = blockIdx.y * BM;
    const int n0  = blockIdx.x * BN;
    const int lr  = tid >> 2;
    const int lc  = (tid & 3) * 4;
    const float* Aptr = A + (size_t)m0 * K;
    const float* Bptr = B + (size_t)n0 * K;

    float acc[8][8];
#pragma unroll
    for (int i = 0; i < 8; ++i)
#pragma unroll
        for (int j = 0; j < 8; ++j) acc[i][j] = 0.f;

    for (int k0 = 0; k0 < K; k0 += BK) {
#pragma unroll
        for (int h = 0; h < 2; ++h) {
            int r = lr + h * 64;
            float4 v = *(const float4*)(Aptr + (size_t)r * K + k0 + lc);
            As[lc + 0][r] = v.x; As[lc + 1][r] = v.y;
            As[lc + 2][r] = v.z; As[lc + 3][r] = v.w;
            float4 w = *(const float4*)(Bptr + (size_t)r * K + k0 + lc);
            Bs[lc + 0][r] = w.x; Bs[lc + 1][r] = w.y;
            Bs[lc + 2][r] = w.z; Bs[lc + 3][r] = w.w;
        }
        __syncthreads();
#pragma unroll
        for (int kk = 0; kk < BK; ++kk) {
            float ra[8], rb[8];
            *(float4*)&ra[0] = *(const float4*)&As[kk][ty * 8];
            *(float4*)&ra[4] = *(const float4*)&As[kk][ty * 8 + 4];
            *(float4*)&rb[0] = *(const float4*)&Bs[kk][tx * 8];
            *(float4*)&rb[4] = *(const float4*)&Bs[kk][tx * 8 + 4];
#pragma unroll
            for (int i = 0; i < 8; ++i)
#pragma unroll
                for (int j = 0; j < 8; ++j)
                    acc[i][j] = fmaf(ra[i], rb[j], acc[i][j]);
        }
        __syncthreads();
    }
    float bi[8];
#pragma unroll
    for (int j = 0; j < 8; ++j) {
        int n = n0 + tx * 8 + j;
        bi[j] = bias ? ((n < N) ? bias[n] : 0.f) : 0.f;
    }
#pragma unroll
    for (int i = 0; i < 8; ++i) {
        int m = m0 + ty * 8 + i;
        float* crow = C + (size_t)m * ldc + n0 + tx * 8;
#pragma unroll
        for (int jv = 0; jv < 8; jv += 4) {
            float4 w;
            w.x = acc[i][jv + 0] + bi[jv + 0];
            w.y = acc[i][jv + 1] + bi[jv + 1];
            w.z = acc[i][jv + 2] + bi[jv + 2];
            w.w = acc[i][jv + 3] + bi[jv + 3];
            *(float4*)(crow + jv) = w;
        }
    }
}

// ---------------------------------------------------------------------------
// Row L2-normalize + fused bf16 cast. IEEE div/sqrt (matches reference).
// ---------------------------------------------------------------------------
__global__ void l2norm_rows_kernel(const float* __restrict__ src,
                                   float* __restrict__ dstf,
                                   __nv_bfloat16* __restrict__ dstb, int rows)
{
    int row  = blockIdx.x * 8 + (threadIdx.x >> 5);
    int lane = threadIdx.x & 31;
    if (row >= rows) return;
    const float4* p = (const float4*)(src + (size_t)row * D_DIM);
    float4 v0 = p[lane];
    float4 v1 = p[lane + 32];
    float ss = v0.x * v0.x + v0.y * v0.y + v0.z * v0.z + v0.w * v0.w
             + v1.x * v1.x + v1.y * v1.y + v1.z * v1.z + v1.w * v1.w;
#pragma unroll
    for (int off = 16; off > 0; off >>= 1)
        ss += __shfl_xor_sync(0xffffffffu, ss, off);
    float den = fmaxf(__fsqrt_rn(ss), 1e-12f);
    v0.x = __fdiv_rn(v0.x, den); v0.y = __fdiv_rn(v0.y, den);
    v0.z = __fdiv_rn(v0.z, den); v0.w = __fdiv_rn(v0.w, den);
    v1.x = __fdiv_rn(v1.x, den); v1.y = __fdiv_rn(v1.y, den);
    v1.z = __fdiv_rn(v1.z, den); v1.w = __fdiv_rn(v1.w, den);
    float4* q = (float4*)(dstf + (size_t)row * D_DIM);
    q[lane]      = v0;
    q[lane + 32] = v1;
    __nv_bfloat162* d2 = (__nv_bfloat162*)(dstb + (size_t)row * D_DIM);
    d2[lane * 2 + 0]        = __floats2bfloat162_rn(v0.x, v0.y);
    d2[lane * 2 + 1]        = __floats2bfloat162_rn(v0.z, v0.w);
    d2[(lane + 32) * 2 + 0] = __floats2bfloat162_rn(v1.x, v1.y);
    d2[(lane + 32) * 2 + 1] = __floats2bfloat162_rn(v1.z, v1.w);
}

// ---------------------------------------------------------------------------
// Fused candidate + exact rescore + top-8, one block (256 thr) per row.
// ---------------------------------------------------------------------------
__device__ __forceinline__ bool tk_better(float s1, int i1, float s2, int i2)
{
    return (s1 > s2) || (s1 == s2 && i1 < i2);
}

__device__ __forceinline__ float hmax8(uint4 pk)
{
    const __half2* h = (const __half2*)&pk;
    __half2 m01 = __hmax2(h[0], h[1]);
    __half2 m23 = __hmax2(h[2], h[3]);
    __half2 m   = __hmax2(m01, m23);
    return fmaxf(__low2float(m), __high2float(m));
}

__global__ void __launch_bounds__(256) candres_kernel(
    const __half* __restrict__ tmax, const float* __restrict__ q,
    const float* __restrict__ kn,
    float* __restrict__ out_scores, int* __restrict__ topi)
{
    __shared__ __align__(16) float qs[D_DIM];
    __shared__ float st[32][257];          // staged kn rows (conflict-free stride)
    __shared__ float thmax[256];
    __shared__ float sT;
    __shared__ int   scnt;
    __shared__ int   chid[MAXCH];
    __shared__ float cs[MAXCH * 8];
    __shared__ int   ci[MAXCH * 8];
    __shared__ float rs[8];
    __shared__ int   rk[8];
    __shared__ int   rp[8];

    const int r    = blockIdx.x;
    const int tid  = threadIdx.x;
    const int wid  = tid >> 5;
    const int lane = tid & 31;
    const uint4* trow = (const uint4*)(tmax + (size_t)r * N_TCH);

    // q row to smem
    if (tid < 64) ((float4*)qs)[tid] = ((const float4*)(q + (size_t)r * D_DIM))[tid];

    // Pass 1: per-thread slice max over chunk maxes
    float tm = -FLT_MAX;
    for (int g = tid; g < NG8; g += 256)
        tm = fmaxf(tm, hmax8(trow[g]));
    thmax[tid] = tm;
    if (tid == 0) scnt = 0;
    __syncthreads();

    // T = 16th largest of the 256 slice maxes (<= true 16th element value)
    if (tid < 32) {
        float l[8];
#pragma unroll
        for (int j = 0; j < 8; ++j) l[j] = thmax[tid * 8 + j];
        float T = -FLT_MAX;
        for (int it = 0; it < NCAND; ++it) {
            float lm = -FLT_MAX;
#pragma unroll
            for (int j = 0; j < 8; ++j) lm = fmaxf(lm, l[j]);
#pragma unroll
            for (int off = 16; off > 0; off >>= 1)
                lm = fmaxf(lm, __shfl_xor_sync(0xffffffffu, lm, off));
            bool done = false;
#pragma unroll
            for (int j = 0; j < 8; ++j)
                if (!done && l[j] == lm) { l[j] = -FLT_MAX; done = true; }
            T = lm;
        }
        if (tid == 0) sT = T;
    }
    __syncthreads();
    const float T = sT;

    // Pass 2: collect hot chunk ids (row cache-hot, ~25 hits)
    for (int g = tid; g < NG8; g += 256) {
        uint4 pk = trow[g];
        if (hmax8(pk) >= T) {
            const __half2* h = (const __half2*)&pk;
#pragma unroll
            for (int v = 0; v < 4; ++v) {
                float2 f = __half22float2(h[v]);
                if (f.x >= T) { int p = atomicAdd(&scnt, 1); if (p < MAXCH) chid[p] = g * 8 + v * 2; }
                if (f.y >= T) { int p = atomicAdd(&scnt, 1); if (p < MAXCH) chid[p] = g * 8 + v * 2 + 1; }
            }
        }
    }
    __syncthreads();
    const int CE = min(scnt, MAXCH) * 8;

    // Tiled exact rescore: stage 32 candidate rows coalesced, then serial
    // ascending-k fma chain from smem (identical numerics to prior rounds).
    for (int t0 = 0; t0 < CE; t0 += 32) {
        const int nr = min(32, CE - t0);
#pragma unroll
        for (int j = 0; j < 8; ++j) {
            int u  = j * 256 + tid;
            int lr = u >> 6;
            int lc = u & 63;
            if (lr < nr) {
                int e = t0 + lr;
                int n = chid[e >> 3] * 8 + (e & 7);
                float4 v = ((const float4*)(kn + (size_t)n * D_DIM))[lc];
                st[lr][lc * 4 + 0] = v.x; st[lr][lc * 4 + 1] = v.y;
                st[lr][lc * 4 + 2] = v.z; st[lr][lc * 4 + 3] = v.w;
            }
        }
        __syncthreads();
        if (tid < nr) {
            int e = t0 + tid;
            int n = chid[e >> 3] * 8 + (e & 7);
            float acc = 0.f;
#pragma unroll 8
            for (int k = 0; k < D_DIM; ++k)
                acc = fmaf(qs[k], st[tid][k], acc);
            cs[e] = acc; ci[e] = n;
        }
        __syncthreads();
    }

    // Exact (score, index) top-8 via warp-shuffle reductions (2 barriers/iter)
    for (int it = 0; it < TOPK; ++it) {
        float bs = -FLT_MAX; int bk = 0x7fffffff; int bp = -1;
        for (int i = tid; i < CE; i += 256)
            if (tk_better(cs[i], ci[i], bs, bk)) { bs = cs[i]; bk = ci[i]; bp = i; }
#pragma unroll
        for (int off = 16; off > 0; off >>= 1) {
            float os = __shfl_down_sync(0xffffffffu, bs, off);
            int   ok = __shfl_down_sync(0xffffffffu, bk, off);
            int   op = __shfl_down_sync(0xffffffffu, bp, off);
            if (tk_better(os, ok, bs, bk)) { bs = os; bk = ok; bp = op; }
        }
        if (lane == 0) { rs[wid] = bs; rk[wid] = bk; rp[wid] = bp; }
        __syncthreads();
        if (tid < 8) {
            bs = rs[tid]; bk = rk[tid]; bp = rp[tid];
#pragma unroll
            for (int off = 4; off > 0; off >>= 1) {
                float os = __shfl_down_sync(0x000000ffu, bs, off, 8);
                int   ok = __shfl_down_sync(0x000000ffu, bk, off, 8);
                int   op = __shfl_down_sync(0x000000ffu, bp, off, 8);
                if (tk_better(os, ok, bs, bk)) { bs = os; bk = ok; bp = op; }
            }
            if (tid == 0) {
                out_scores[r * TOPK + it] = bs;
                topi[r * TOPK + it]       = bk;
                if (bp >= 0) { cs[bp] = -FLT_MAX; ci[bp] = 0x7fffffff; }
            }
        }
        __syncthreads();
    }
}

// ---------------------------------------------------------------------------
// usage passthrough + gather
// ---------------------------------------------------------------------------
__global__ void usage_init_kernel(const float* __restrict__ usage, float* __restrict__ out_usage)
{
    int i = blockIdx.x * blockDim.x + threadIdx.x;
    if (i < N_KEYS) out_usage[i] = usage[i];
}

__global__ void gather_kernel(const float* __restrict__ values, const int* __restrict__ topi,
                              float* __restrict__ out_rv, float* __restrict__ out_usage)
{
    int slot = blockIdx.x;
    int idx  = topi[slot];
    if (threadIdx.x == 0) atomicAdd(&out_usage[idx], 1.0f);
    const float4* src = (const float4*)(values + (size_t)idx * V_DIM);
    float4*       dst = (float4*)(out_rv + (size_t)slot * V_DIM);
    dst[threadIdx.x] = src[threadIdx.x];
}

// ---------------------------------------------------------------------------
// Launch
// ---------------------------------------------------------------------------
extern "C" void kernel_launch(void* const* d_in, const int* in_sizes, int n_in,
                              void* d_out, int out_size)
{
    const float* query  = (const float*)d_in[0];
    const float* W      = (const float*)d_in[1];
    const float* bias   = (const float*)d_in[2];
    const float* keys   = (const float*)d_in[3];
    const float* values = (const float*)d_in[4];
    const float* usage  = (const float*)d_in[5];

    float* out       = (float*)d_out;
    float* out_rv    = out;
    float* out_sc    = out + (size_t)B_ROWS * TOPK * V_DIM;
    float* out_usage = out_sc + (size_t)B_ROWS * TOPK;

    float*         q    = nullptr; cudaGetSymbolAddress((void**)&q,    g_q);
    float*         kn   = nullptr; cudaGetSymbolAddress((void**)&kn,   g_kn);
    __nv_bfloat16* ah   = nullptr; cudaGetSymbolAddress((void**)&ah,   g_ah);
    __nv_bfloat16* bh   = nullptr; cudaGetSymbolAddress((void**)&bh,   g_bh);
    __half*        tmx  = nullptr; cudaGetSymbolAddress((void**)&tmx,  g_tmax);
    int*           topi = nullptr; cudaGetSymbolAddress((void**)&topi, g_topi);

    // 1) q = query @ W^T + b
    gemm_nt_kernel<<<dim3(D_DIM / BN, B_ROWS / BM), 256>>>(
        query, W, q, bias, D_DIM, D_DIM, D_DIM);

    // 2) normalize + fused bf16 cast; zero bh pad rows
    l2norm_rows_kernel<<<B_ROWS / 8, 256>>>(q, q, ah, B_ROWS);
    l2norm_rows_kernel<<<(N_KEYS + 7) / 8, 256>>>(keys, kn, bh, N_KEYS);
    cudaMemsetAsync(bh + (size_t)N_KEYS * D_DIM, 0,
                    (size_t)(N_PAD - N_KEYS) * D_DIM * sizeof(__nv_bfloat16));

    // 3) bf16 tensor-core GEMM -> chunk maxes only (no sim matrix)
    simtc_kernel<<<dim3(N_PAD / 128, B_ROWS / 128), 512>>>(ah, bh, tmx);

    // 4) fused threshold + collect + coalesced exact rescore + top-8
    candres_kernel<<<B_ROWS, 256>>>(tmx, q, kn, out_sc, topi);

    // 5) usage + gather
    usage_init_kernel<<<(N_KEYS + 255) / 256, 256>>>(usage, out_usage);
    gather_kernel<<<B_ROWS * TOPK, 64>>>(values, topi, out_rv, out_usage);
}

// round 16
// speedup vs baseline: 1.5613x; 1.0342x over previous
#include <cuda_runtime.h>
#include <cuda_bf16.h>
#include <cuda_fp16.h>
#include <math.h>
#include <float.h>
#include <stdint.h>

// Problem dims (fixed by the dataset)
#define B_ROWS 2048
#define N_KEYS 50000
#define D_DIM  256
#define V_DIM  256
#define TOPK   8
#define NCAND  16
#define N_PAD  50048   // 391 * 128
#define N_TCH  6256    // chunk (8-col) maxes per row; ids >= 6250 poisoned -inf
#define NG8    782     // N_TCH / 8 uint4 groups
#define MAXCH  128     // per-row collected-chunk cap (expected ~25)

// ---------------------------------------------------------------------------
// Scratch (static __device__ arrays; allocation is banned)
// ---------------------------------------------------------------------------
__device__ float          g_q[B_ROWS * D_DIM];               // q_norm
__device__ float          g_kn[(size_t)N_KEYS * D_DIM];      // k_norm
__device__ __nv_bfloat16  g_ah[(size_t)B_ROWS * D_DIM];      // bf16(q_norm)
__device__ __nv_bfloat16  g_bh[(size_t)N_PAD * D_DIM];       // bf16(k_norm), pad rows zero
__device__ __half         g_tmax[(size_t)B_ROWS * N_TCH];    // chunk maxes (~26 MB)
__device__ int            g_topi[B_ROWS * TOPK];

// ---------------------------------------------------------------------------
// smem/cp.async/ldmatrix helpers
// ---------------------------------------------------------------------------
__device__ __forceinline__ uint32_t smem_u32(const void* p)
{
    uint32_t a;
    asm("{ .reg .u64 t; cvta.to.shared.u64 t, %1; cvt.u32.u64 %0, t; }" : "=r"(a) : "l"(p));
    return a;
}
__device__ __forceinline__ void cp_async16(uint32_t s, const void* g)
{
    asm volatile("cp.async.cg.shared.global [%0], [%1], 16;" :: "r"(s), "l"(g));
}
#define CP_COMMIT() asm volatile("cp.async.commit_group;")
#define CP_WAIT(n)  asm volatile("cp.async.wait_group %0;" :: "n"(n))

__device__ __forceinline__ void ldsm_x4(uint32_t& r0, uint32_t& r1,
                                        uint32_t& r2, uint32_t& r3, uint32_t addr)
{
    asm volatile("ldmatrix.sync.aligned.m8n8.x4.shared.b16 {%0,%1,%2,%3}, [%4];"
                 : "=r"(r0), "=r"(r1), "=r"(r2), "=r"(r3) : "r"(addr));
}

// ---------------------------------------------------------------------------
// bf16 mma.sync GEMM -> per-8-col chunk maxes ONLY (no sim matrix).
// CTA tile 128x128, 256 threads, 8 warps (2x4), warp tile 64x32, BK=32.
// Larger warp tiles cut fragment smem traffic: 48 KB/chunk vs 64 KB at 32x32.
// ---------------------------------------------------------------------------
#define KST 40

__global__ void __launch_bounds__(256, 2) simtc_kernel(
    const __nv_bfloat16* __restrict__ Ah,
    const __nv_bfloat16* __restrict__ Bh,
    __half* __restrict__ tmax)
{
    __shared__ __align__(16) uint16_t As[2][128][KST];
    __shared__ __align__(16) uint16_t Bs[2][128][KST];
    __shared__ __align__(16) __half   tmx_s[128][16];

    const int tid  = threadIdx.x;
    const int wid  = tid >> 5;
    const int lane = tid & 31;
    const int wm   = (wid >> 2) * 64;  // warp m offset: 0 or 64
    const int wn   = (wid & 3) * 32;   // warp n offset: 0,32,64,96
    const int m0   = blockIdx.y * 128;
    const int n0   = blockIdx.x * 128;

    const uint32_t sA = smem_u32(As);
    const uint32_t sB = smem_u32(Bs);
    const int lrow = tid >> 2;          // 0..63
    const int lcu  = tid & 3;           // 16B unit

    // ldmatrix lane address components (bit-identical fragment mapping)
    const int aRow = lane & 15;
    const int aKof = (lane >> 4) << 3;
    const int bIdx = lane >> 3;
    const int bRow = ((bIdx >> 1) << 3) + (lane & 7);
    const int bKof = (bIdx & 1) << 3;

    float c[4][4][4];
#pragma unroll
    for (int i = 0; i < 4; ++i)
#pragma unroll
        for (int j = 0; j < 4; ++j)
#pragma unroll
            for (int v = 0; v < 4; ++v) c[i][j][v] = 0.f;

    auto load_chunk = [&](int buf, int kc) {
#pragma unroll
        for (int h = 0; h < 2; ++h) {
            int row = lrow + h * 64;
            uint32_t so = (uint32_t)(((buf * 128 + row) * KST + lcu * 8) * 2);
            cp_async16(sA + so, Ah + (size_t)(m0 + row) * D_DIM + kc * 32 + lcu * 8);
            cp_async16(sB + so, Bh + (size_t)(n0 + row) * D_DIM + kc * 32 + lcu * 8);
        }
    };

    auto compute_chunk = [&](int buf) {
#pragma unroll
        for (int ks = 0; ks < 2; ++ks) {
            const int k0 = ks * 16;
            uint32_t a[4][4];
#pragma unroll
            for (int mt = 0; mt < 4; ++mt) {
                uint32_t addr = sA + (uint32_t)(((buf * 128 + wm + mt * 16 + aRow) * KST
                                                 + k0 + aKof) * 2);
                ldsm_x4(a[mt][0], a[mt][1], a[mt][2], a[mt][3], addr);
            }
            uint32_t b[4][2];
#pragma unroll
            for (int np = 0; np < 2; ++np) {
                uint32_t addr = sB + (uint32_t)(((buf * 128 + wn + np * 16 + bRow) * KST
                                                 + k0 + bKof) * 2);
                uint32_t r0, r1, r2, r3;
                ldsm_x4(r0, r1, r2, r3, addr);
                b[np * 2][0] = r0; b[np * 2][1] = r1;
                b[np * 2 + 1][0] = r2; b[np * 2 + 1][1] = r3;
            }
#pragma unroll
            for (int mt = 0; mt < 4; ++mt)
#pragma unroll
                for (int nt = 0; nt < 4; ++nt)
                    asm volatile(
                        "mma.sync.aligned.m16n8k16.row.col.f32.bf16.bf16.f32 "
                        "{%0,%1,%2,%3}, {%4,%5,%6,%7}, {%8,%9}, {%0,%1,%2,%3};"
                        : "+f"(c[mt][nt][0]), "+f"(c[mt][nt][1]),
                          "+f"(c[mt][nt][2]), "+f"(c[mt][nt][3])
                        : "r"(a[mt][0]), "r"(a[mt][1]), "r"(a[mt][2]), "r"(a[mt][3]),
                          "r"(b[nt][0]), "r"(b[nt][1]));
        }
    };

    load_chunk(0, 0); CP_COMMIT();
    load_chunk(1, 1); CP_COMMIT();

    const int nchunk = D_DIM / 32;     // 8
#pragma unroll
    for (int t = 0; t < nchunk; ++t) {
        if (t == nchunk - 1) { CP_WAIT(0); } else { CP_WAIT(1); }
        __syncthreads();
        compute_chunk(t & 1);
        __syncthreads();
        if (t + 2 < nchunk) { load_chunk(t & 1, t + 2); CP_COMMIT(); }
    }

    // Epilogue: per-(row, 8-col chunk) maxes via quad shuffles -> smem stage
    const __half NEGINF = __ushort_as_half((unsigned short)0xFC00);
    const int gid = lane >> 2;
#pragma unroll
    for (int mt = 0; mt < 4; ++mt) {
        int r = wm + mt * 16 + gid;
#pragma unroll
        for (int nt = 0; nt < 4; ++nt) {
            float mlo = fmaxf(c[mt][nt][0], c[mt][nt][1]);
            float mhi = fmaxf(c[mt][nt][2], c[mt][nt][3]);
            mlo = fmaxf(mlo, __shfl_xor_sync(0xffffffffu, mlo, 1));
            mlo = fmaxf(mlo, __shfl_xor_sync(0xffffffffu, mlo, 2));
            mhi = fmaxf(mhi, __shfl_xor_sync(0xffffffffu, mhi, 1));
            mhi = fmaxf(mhi, __shfl_xor_sync(0xffffffffu, mhi, 2));
            if ((lane & 3) == 0) {
                int  chc = (wn >> 3) + nt;                 // 0..15 within CTA
                bool pad = (n0 + wn + nt * 8) >= N_KEYS;   // chunk-aligned
                tmx_s[r][chc]     = pad ? NEGINF : __float2half_rn(mlo);
                tmx_s[r + 8][chc] = pad ? NEGINF : __float2half_rn(mhi);
            }
        }
    }
    __syncthreads();
    // Coalesced copy-out: 2048 halves = 512 x 8B (256 threads x 2)
#pragma unroll
    for (int h = 0; h < 2; ++h) {
        int u = tid + h * 256;
        int row = u >> 2, cq = u & 3;
        uint2 v = *(const uint2*)&tmx_s[row][cq * 4];
        *(uint2*)(tmax + (size_t)(m0 + row) * N_TCH + (n0 >> 3) + cq * 4) = v;
    }
}

// ---------------------------------------------------------------------------
// fp32 NT SGEMM (small q = query @ W^T + b only)
// ---------------------------------------------------------------------------
#define BM 128
#define BN 128
#define BK 16

__global__ void __launch_bounds__(256) gemm_nt_kernel(
    const float* __restrict__ A, const float* __restrict__ B,
    float* __restrict__ C, const float* __restrict__ bias,
    int N, int K, int ldc)
{
    __shared__ __align__(16) float As[BK][BM];
    __shared__ __align__(16) float Bs[BK][BN];
    const int tid = threadIdx.x;
    const int tx  = tid & 15;
    const int ty  = tid >> 4;
    const int m0  = blockIdx.y * BM;
    const int n0  = blockIdx.x * BN;
    const int lr  = tid >> 2;
    const int lc  = (tid & 3) * 4;
    const float* Aptr = A + (size_t)m0 * K;
    const float* Bptr = B + (size_t)n0 * K;

    float acc[8][8];
#pragma unroll
    for (int i = 0; i < 8; ++i)
#pragma unroll
        for (int j = 0; j < 8; ++j) acc[i][j] = 0.f;

    for (int k0 = 0; k0 < K; k0 += BK) {
#pragma unroll
        for (int h = 0; h < 2; ++h) {
            int r = lr + h * 64;
            float4 v = *(const float4*)(Aptr + (size_t)r * K + k0 + lc);
            As[lc + 0][r] = v.x; As[lc + 1][r] = v.y;
            As[lc + 2][r] = v.z; As[lc + 3][r] = v.w;
            float4 w = *(const float4*)(Bptr + (size_t)r * K + k0 + lc);
            Bs[lc + 0][r] = w.x; Bs[lc + 1][r] = w.y;
            Bs[lc + 2][r] = w.z; Bs[lc + 3][r] = w.w;
        }
        __syncthreads();
#pragma unroll
        for (int kk = 0; kk < BK; ++kk) {
            float ra[8], rb[8];
            *(float4*)&ra[0] = *(const float4*)&As[kk][ty * 8];
            *(float4*)&ra[4] = *(const float4*)&As[kk][ty * 8 + 4];
            *(float4*)&rb[0] = *(const float4*)&Bs[kk][tx * 8];
            *(float4*)&rb[4] = *(const float4*)&Bs[kk][tx * 8 + 4];
#pragma unroll
            for (int i = 0; i < 8; ++i)
#pragma unroll
                for (int j = 0; j < 8; ++j)
                    acc[i][j] = fmaf(ra[i], rb[j], acc[i][j]);
        }
        __syncthreads();
    }
    float bi[8];
#pragma unroll
    for (int j = 0; j < 8; ++j) {
        int n = n0 + tx * 8 + j;
        bi[j] = bias ? ((n < N) ? bias[n] : 0.f) : 0.f;
    }
#pragma unroll
    for (int i = 0; i < 8; ++i) {
        int m = m0 + ty * 8 + i;
        float* crow = C + (size_t)m * ldc + n0 + tx * 8;
#pragma unroll
        for (int jv = 0; jv < 8; jv += 4) {
            float4 w;
            w.x = acc[i][jv + 0] + bi[jv + 0];
            w.y = acc[i][jv + 1] + bi[jv + 1];
            w.z = acc[i][jv + 2] + bi[jv + 2];
            w.w = acc[i][jv + 3] + bi[jv + 3];
            *(float4*)(crow + jv) = w;
        }
    }
}

// ---------------------------------------------------------------------------
// Row L2-normalize + fused bf16 cast. IEEE div/sqrt (matches reference).
// ---------------------------------------------------------------------------
__global__ void l2norm_rows_kernel(const float* __restrict__ src,
                                   float* __restrict__ dstf,
                                   __nv_bfloat16* __restrict__ dstb, int rows)
{
    int row  = blockIdx.x * 8 + (threadIdx.x >> 5);
    int lane = threadIdx.x & 31;
    if (row >= rows) return;
    const float4* p = (const float4*)(src + (size_t)row * D_DIM);
    float4 v0 = p[lane];
    float4 v1 = p[lane + 32];
    float ss = v0.x * v0.x + v0.y * v0.y + v0.z * v0.z + v0.w * v0.w
             + v1.x * v1.x + v1.y * v1.y + v1.z * v1.z + v1.w * v1.w;
#pragma unroll
    for (int off = 16; off > 0; off >>= 1)
        ss += __shfl_xor_sync(0xffffffffu, ss, off);
    float den = fmaxf(__fsqrt_rn(ss), 1e-12f);
    v0.x = __fdiv_rn(v0.x, den); v0.y = __fdiv_rn(v0.y, den);
    v0.z = __fdiv_rn(v0.z, den); v0.w = __fdiv_rn(v0.w, den);
    v1.x = __fdiv_rn(v1.x, den); v1.y = __fdiv_rn(v1.y, den);
    v1.z = __fdiv_rn(v1.z, den); v1.w = __fdiv_rn(v1.w, den);
    float4* q = (float4*)(dstf + (size_t)row * D_DIM);
    q[lane]      = v0;
    q[lane + 32] = v1;
    __nv_bfloat162* d2 = (__nv_bfloat162*)(dstb + (size_t)row * D_DIM);
    d2[lane * 2 + 0]        = __floats2bfloat162_rn(v0.x, v0.y);
    d2[lane * 2 + 1]        = __floats2bfloat162_rn(v0.z, v0.w);
    d2[(lane + 32) * 2 + 0] = __floats2bfloat162_rn(v1.x, v1.y);
    d2[(lane + 32) * 2 + 1] = __floats2bfloat162_rn(v1.z, v1.w);
}

// ---------------------------------------------------------------------------
// Fused candidate + exact rescore + top-8, one block (256 thr) per row.
// ---------------------------------------------------------------------------
__device__ __forceinline__ bool tk_better(float s1, int i1, float s2, int i2)
{
    return (s1 > s2) || (s1 == s2 && i1 < i2);
}

__device__ __forceinline__ float hmax8(uint4 pk)
{
    const __half2* h = (const __half2*)&pk;
    __half2 m01 = __hmax2(h[0], h[1]);
    __half2 m23 = __hmax2(h[2], h[3]);
    __half2 m   = __hmax2(m01, m23);
    return fmaxf(__low2float(m), __high2float(m));
}

__global__ void __launch_bounds__(256) candres_kernel(
    const __half* __restrict__ tmax, const float* __restrict__ q,
    const float* __restrict__ kn,
    float* __restrict__ out_scores, int* __restrict__ topi)
{
    __shared__ __align__(16) float qs[D_DIM];
    __shared__ float st[32][257];          // staged kn rows (conflict-free stride)
    __shared__ float thmax[256];
    __shared__ float sT;
    __shared__ int   scnt;
    __shared__ int   chid[MAXCH];
    __shared__ float cs[MAXCH * 8];
    __shared__ int   ci[MAXCH * 8];
    __shared__ float rs[8];
    __shared__ int   rk[8];
    __shared__ int   rp[8];

    const int r    = blockIdx.x;
    const int tid  = threadIdx.x;
    const int wid  = tid >> 5;
    const int lane = tid & 31;
    const uint4* trow = (const uint4*)(tmax + (size_t)r * N_TCH);

    // q row to smem
    if (tid < 64) ((float4*)qs)[tid] = ((const float4*)(q + (size_t)r * D_DIM))[tid];

    // Pass 1: per-thread slice max over chunk maxes
    float tm = -FLT_MAX;
    for (int g = tid; g < NG8; g += 256)
        tm = fmaxf(tm, hmax8(trow[g]));
    thmax[tid] = tm;
    if (tid == 0) scnt = 0;
    __syncthreads();

    // T = 16th largest of the 256 slice maxes (<= true 16th element value)
    if (tid < 32) {
        float l[8];
#pragma unroll
        for (int j = 0; j < 8; ++j) l[j] = thmax[tid * 8 + j];
        float T = -FLT_MAX;
        for (int it = 0; it < NCAND; ++it) {
            float lm = -FLT_MAX;
#pragma unroll
            for (int j = 0; j < 8; ++j) lm = fmaxf(lm, l[j]);
#pragma unroll
            for (int off = 16; off > 0; off >>= 1)
                lm = fmaxf(lm, __shfl_xor_sync(0xffffffffu, lm, off));
            bool done = false;
#pragma unroll
            for (int j = 0; j < 8; ++j)
                if (!done && l[j] == lm) { l[j] = -FLT_MAX; done = true; }
            T = lm;
        }
        if (tid == 0) sT = T;
    }
    __syncthreads();
    const float T = sT;

    // Pass 2: collect hot chunk ids (row cache-hot, ~25 hits)
    for (int g = tid; g < NG8; g += 256) {
        uint4 pk = trow[g];
        if (hmax8(pk) >= T) {
            const __half2* h = (const __half2*)&pk;
#pragma unroll
            for (int v = 0; v < 4; ++v) {
                float2 f = __half22float2(h[v]);
                if (f.x >= T) { int p = atomicAdd(&scnt, 1); if (p < MAXCH) chid[p] = g * 8 + v * 2; }
                if (f.y >= T) { int p = atomicAdd(&scnt, 1); if (p < MAXCH) chid[p] = g * 8 + v * 2 + 1; }
            }
        }
    }
    __syncthreads();
    const int CE = min(scnt, MAXCH) * 8;

    // Tiled exact rescore: stage 32 candidate rows coalesced, then serial
    // ascending-k fma chain from smem (identical numerics to prior rounds).
    for (int t0 = 0; t0 < CE; t0 += 32) {
        const int nr = min(32, CE - t0);
#pragma unroll
        for (int j = 0; j < 8; ++j) {
            int u  = j * 256 + tid;
            int lr = u >> 6;
            int lc = u & 63;
            if (lr < nr) {
                int e = t0 + lr;
                int n = chid[e >> 3] * 8 + (e & 7);
                float4 v = ((const float4*)(kn + (size_t)n * D_DIM))[lc];
                st[lr][lc * 4 + 0] = v.x; st[lr][lc * 4 + 1] = v.y;
                st[lr][lc * 4 + 2] = v.z; st[lr][lc * 4 + 3] = v.w;
            }
        }
        __syncthreads();
        if (tid < nr) {
            int e = t0 + tid;
            int n = chid[e >> 3] * 8 + (e & 7);
            float acc = 0.f;
#pragma unroll 8
            for (int k = 0; k < D_DIM; ++k)
                acc = fmaf(qs[k], st[tid][k], acc);
            cs[e] = acc; ci[e] = n;
        }
        __syncthreads();
    }

    // Exact (score, index) top-8 via warp-shuffle reductions (2 barriers/iter)
    for (int it = 0; it < TOPK; ++it) {
        float bs = -FLT_MAX; int bk = 0x7fffffff; int bp = -1;
        for (int i = tid; i < CE; i += 256)
            if (tk_better(cs[i], ci[i], bs, bk)) { bs = cs[i]; bk = ci[i]; bp = i; }
#pragma unroll
        for (int off = 16; off > 0; off >>= 1) {
            float os = __shfl_down_sync(0xffffffffu, bs, off);
            int   ok = __shfl_down_sync(0xffffffffu, bk, off);
            int   op = __shfl_down_sync(0xffffffffu, bp, off);
            if (tk_better(os, ok, bs, bk)) { bs = os; bk = ok; bp = op; }
        }
        if (lane == 0) { rs[wid] = bs; rk[wid] = bk; rp[wid] = bp; }
        __syncthreads();
        if (tid < 8) {
            bs = rs[tid]; bk = rk[tid]; bp = rp[tid];
#pragma unroll
            for (int off = 4; off > 0; off >>= 1) {
                float os = __shfl_down_sync(0x000000ffu, bs, off, 8);
                int   ok = __shfl_down_sync(0x000000ffu, bk, off, 8);
                int   op = __shfl_down_sync(0x000000ffu, bp, off, 8);
                if (tk_better(os, ok, bs, bk)) { bs = os; bk = ok; bp = op; }
            }
            if (tid == 0) {
                out_scores[r * TOPK + it] = bs;
                topi[r * TOPK + it]       = bk;
                if (bp >= 0) { cs[bp] = -FLT_MAX; ci[bp] = 0x7fffffff; }
            }
        }
        __syncthreads();
    }
}

// ---------------------------------------------------------------------------
// usage passthrough + gather
// ---------------------------------------------------------------------------
__global__ void usage_init_kernel(const float* __restrict__ usage, float* __restrict__ out_usage)
{
    int i = blockIdx.x * blockDim.x + threadIdx.x;
    if (i < N_KEYS) out_usage[i] = usage[i];
}

__global__ void gather_kernel(const float* __restrict__ values, const int* __restrict__ topi,
                              float* __restrict__ out_rv, float* __restrict__ out_usage)
{
    int slot = blockIdx.x;
    int idx  = topi[slot];
    if (threadIdx.x == 0) atomicAdd(&out_usage[idx], 1.0f);
    const float4* src = (const float4*)(values + (size_t)idx * V_DIM);
    float4*       dst = (float4*)(out_rv + (size_t)slot * V_DIM);
    dst[threadIdx.x] = src[threadIdx.x];
}

// ---------------------------------------------------------------------------
// Launch
// ---------------------------------------------------------------------------
extern "C" void kernel_launch(void* const* d_in, const int* in_sizes, int n_in,
                              void* d_out, int out_size)
{
    const float* query  = (const float*)d_in[0];
    const float* W      = (const float*)d_in[1];
    const float* bias   = (const float*)d_in[2];
    const float* keys   = (const float*)d_in[3];
    const float* values = (const float*)d_in[4];
    const float* usage  = (const float*)d_in[5];

    float* out       = (float*)d_out;
    float* out_rv    = out;
    float* out_sc    = out + (size_t)B_ROWS * TOPK * V_DIM;
    float* out_usage = out_sc + (size_t)B_ROWS * TOPK;

    float*         q    = nullptr; cudaGetSymbolAddress((void**)&q,    g_q);
    float*         kn   = nullptr; cudaGetSymbolAddress((void**)&kn,   g_kn);
    __nv_bfloat16* ah   = nullptr; cudaGetSymbolAddress((void**)&ah,   g_ah);
    __nv_bfloat16* bh   = nullptr; cudaGetSymbolAddress((void**)&bh,   g_bh);
    __half*        tmx  = nullptr; cudaGetSymbolAddress((void**)&tmx,  g_tmax);
    int*           topi = nullptr; cudaGetSymbolAddress((void**)&topi, g_topi);

    // 1) q = query @ W^T + b
    gemm_nt_kernel<<<dim3(D_DIM / BN, B_ROWS / BM), 256>>>(
        query, W, q, bias, D_DIM, D_DIM, D_DIM);

    // 2) normalize + fused bf16 cast; zero bh pad rows
    l2norm_rows_kernel<<<B_ROWS / 8, 256>>>(q, q, ah, B_ROWS);
    l2norm_rows_kernel<<<(N_KEYS + 7) / 8, 256>>>(keys, kn, bh, N_KEYS);
    cudaMemsetAsync(bh + (size_t)N_KEYS * D_DIM, 0,
                    (size_t)(N_PAD - N_KEYS) * D_DIM * sizeof(__nv_bfloat16));

    // 3) bf16 tensor-core GEMM -> chunk maxes only (no sim matrix)
    simtc_kernel<<<dim3(N_PAD / 128, B_ROWS / 128), 256>>>(ah, bh, tmx);

    // 4) fused threshold + collect + coalesced exact rescore + top-8
    candres_kernel<<<B_ROWS, 256>>>(tmx, q, kn, out_sc, topi);

    // 5) usage + gather
    usage_init_kernel<<<(N_KEYS + 255) / 256, 256>>>(usage, out_usage);
    gather_kernel<<<B_ROWS * TOPK, 64>>>(values, topi, out_rv, out_usage);
}

// round 17
// speedup vs baseline: 1.6310x; 1.0446x over previous
#include <cuda_runtime.h>
#include <cuda_bf16.h>
#include <cuda_fp16.h>
#include <math.h>
#include <float.h>
#include <stdint.h>

// Problem dims (fixed by the dataset)
#define B_ROWS 2048
#define N_KEYS 50000
#define D_DIM  256
#define V_DIM  256
#define TOPK   8
#define NCAND  16
#define N_PAD  50048   // 391 * 128
#define N_TCH  6256    // chunk (8-col) maxes per row; ids >= 6250 poisoned -inf
#define NG8    782     // N_TCH / 8 uint4 groups
#define MAXCH  128     // per-row collected-chunk cap (expected ~25)

// ---------------------------------------------------------------------------
// Scratch (static __device__ arrays; allocation is banned)
// ---------------------------------------------------------------------------
__device__ float          g_q[B_ROWS * D_DIM];               // q_norm
__device__ float          g_kn[(size_t)N_KEYS * D_DIM];      // k_norm
__device__ __nv_bfloat16  g_ah[(size_t)B_ROWS * D_DIM];      // bf16(q_norm)
__device__ __nv_bfloat16  g_bh[(size_t)N_PAD * D_DIM];       // bf16(k_norm), pad rows zero
__device__ __half         g_tmax[(size_t)B_ROWS * N_TCH];    // chunk maxes (~26 MB)
__device__ int            g_topi[B_ROWS * TOPK];

// ---------------------------------------------------------------------------
// smem/cp.async/ldmatrix helpers
// ---------------------------------------------------------------------------
__device__ __forceinline__ uint32_t smem_u32(const void* p)
{
    uint32_t a;
    asm("{ .reg .u64 t; cvta.to.shared.u64 t, %1; cvt.u32.u64 %0, t; }" : "=r"(a) : "l"(p));
    return a;
}
__device__ __forceinline__ void cp_async16(uint32_t s, const void* g)
{
    asm volatile("cp.async.cg.shared.global [%0], [%1], 16;" :: "r"(s), "l"(g));
}
#define CP_COMMIT() asm volatile("cp.async.commit_group;")
#define CP_WAIT(n)  asm volatile("cp.async.wait_group %0;" :: "n"(n))

__device__ __forceinline__ void ldsm_x4(uint32_t& r0, uint32_t& r1,
                                        uint32_t& r2, uint32_t& r3, uint32_t addr)
{
    asm volatile("ldmatrix.sync.aligned.m8n8.x4.shared.b16 {%0,%1,%2,%3}, [%4];"
                 : "=r"(r0), "=r"(r1), "=r"(r2), "=r"(r3) : "r"(addr));
}

// ---------------------------------------------------------------------------
// bf16 mma.sync GEMM -> per-8-col chunk maxes ONLY (no sim matrix).
// CTA tile 128x128, 256 threads, 8 warps (2x4), warp tile 64x32, BK=32.
// ---------------------------------------------------------------------------
#define KST 40

__global__ void __launch_bounds__(256, 2) simtc_kernel(
    const __nv_bfloat16* __restrict__ Ah,
    const __nv_bfloat16* __restrict__ Bh,
    __half* __restrict__ tmax)
{
    __shared__ __align__(16) uint16_t As[2][128][KST];
    __shared__ __align__(16) uint16_t Bs[2][128][KST];
    __shared__ __align__(16) __half   tmx_s[128][16];

    const int tid  = threadIdx.x;
    const int wid  = tid >> 5;
    const int lane = tid & 31;
    const int wm   = (wid >> 2) * 64;  // warp m offset: 0 or 64
    const int wn   = (wid & 3) * 32;   // warp n offset: 0,32,64,96
    const int m0   = blockIdx.y * 128;
    const int n0   = blockIdx.x * 128;

    const uint32_t sA = smem_u32(As);
    const uint32_t sB = smem_u32(Bs);
    const int lrow = tid >> 2;          // 0..63
    const int lcu  = tid & 3;           // 16B unit

    // ldmatrix lane address components (bit-identical fragment mapping)
    const int aRow = lane & 15;
    const int aKof = (lane >> 4) << 3;
    const int bIdx = lane >> 3;
    const int bRow = ((bIdx >> 1) << 3) + (lane & 7);
    const int bKof = (bIdx & 1) << 3;

    float c[4][4][4];
#pragma unroll
    for (int i = 0; i < 4; ++i)
#pragma unroll
        for (int j = 0; j < 4; ++j)
#pragma unroll
            for (int v = 0; v < 4; ++v) c[i][j][v] = 0.f;

    auto load_chunk = [&](int buf, int kc) {
#pragma unroll
        for (int h = 0; h < 2; ++h) {
            int row = lrow + h * 64;
            uint32_t so = (uint32_t)(((buf * 128 + row) * KST + lcu * 8) * 2);
            cp_async16(sA + so, Ah + (size_t)(m0 + row) * D_DIM + kc * 32 + lcu * 8);
            cp_async16(sB + so, Bh + (size_t)(n0 + row) * D_DIM + kc * 32 + lcu * 8);
        }
    };

    auto compute_chunk = [&](int buf) {
#pragma unroll
        for (int ks = 0; ks < 2; ++ks) {
            const int k0 = ks * 16;
            uint32_t a[4][4];
#pragma unroll
            for (int mt = 0; mt < 4; ++mt) {
                uint32_t addr = sA + (uint32_t)(((buf * 128 + wm + mt * 16 + aRow) * KST
                                                 + k0 + aKof) * 2);
                ldsm_x4(a[mt][0], a[mt][1], a[mt][2], a[mt][3], addr);
            }
            uint32_t b[4][2];
#pragma unroll
            for (int np = 0; np < 2; ++np) {
                uint32_t addr = sB + (uint32_t)(((buf * 128 + wn + np * 16 + bRow) * KST
                                                 + k0 + bKof) * 2);
                uint32_t r0, r1, r2, r3;
                ldsm_x4(r0, r1, r2, r3, addr);
                b[np * 2][0] = r0; b[np * 2][1] = r1;
                b[np * 2 + 1][0] = r2; b[np * 2 + 1][1] = r3;
            }
#pragma unroll
            for (int mt = 0; mt < 4; ++mt)
#pragma unroll
                for (int nt = 0; nt < 4; ++nt)
                    asm volatile(
                        "mma.sync.aligned.m16n8k16.row.col.f32.bf16.bf16.f32 "
                        "{%0,%1,%2,%3}, {%4,%5,%6,%7}, {%8,%9}, {%0,%1,%2,%3};"
                        : "+f"(c[mt][nt][0]), "+f"(c[mt][nt][1]),
                          "+f"(c[mt][nt][2]), "+f"(c[mt][nt][3])
                        : "r"(a[mt][0]), "r"(a[mt][1]), "r"(a[mt][2]), "r"(a[mt][3]),
                          "r"(b[nt][0]), "r"(b[nt][1]));
        }
    };

    load_chunk(0, 0); CP_COMMIT();
    load_chunk(1, 1); CP_COMMIT();

    const int nchunk = D_DIM / 32;     // 8
#pragma unroll
    for (int t = 0; t < nchunk; ++t) {
        if (t == nchunk - 1) { CP_WAIT(0); } else { CP_WAIT(1); }
        __syncthreads();
        compute_chunk(t & 1);
        __syncthreads();
        if (t + 2 < nchunk) { load_chunk(t & 1, t + 2); CP_COMMIT(); }
    }

    // Epilogue: per-(row, 8-col chunk) maxes via quad shuffles -> smem stage
    const __half NEGINF = __ushort_as_half((unsigned short)0xFC00);
    const int gid = lane >> 2;
#pragma unroll
    for (int mt = 0; mt < 4; ++mt) {
        int r = wm + mt * 16 + gid;
#pragma unroll
        for (int nt = 0; nt < 4; ++nt) {
            float mlo = fmaxf(c[mt][nt][0], c[mt][nt][1]);
            float mhi = fmaxf(c[mt][nt][2], c[mt][nt][3]);
            mlo = fmaxf(mlo, __shfl_xor_sync(0xffffffffu, mlo, 1));
            mlo = fmaxf(mlo, __shfl_xor_sync(0xffffffffu, mlo, 2));
            mhi = fmaxf(mhi, __shfl_xor_sync(0xffffffffu, mhi, 1));
            mhi = fmaxf(mhi, __shfl_xor_sync(0xffffffffu, mhi, 2));
            if ((lane & 3) == 0) {
                int  chc = (wn >> 3) + nt;                 // 0..15 within CTA
                bool pad = (n0 + wn + nt * 8) >= N_KEYS;   // chunk-aligned
                tmx_s[r][chc]     = pad ? NEGINF : __float2half_rn(mlo);
                tmx_s[r + 8][chc] = pad ? NEGINF : __float2half_rn(mhi);
            }
        }
    }
    __syncthreads();
    // Coalesced copy-out: 2048 halves = 512 x 8B (256 threads x 2)
#pragma unroll
    for (int h = 0; h < 2; ++h) {
        int u = tid + h * 256;
        int row = u >> 2, cq = u & 3;
        uint2 v = *(const uint2*)&tmx_s[row][cq * 4];
        *(uint2*)(tmax + (size_t)(m0 + row) * N_TCH + (n0 >> 3) + cq * 4) = v;
    }
}

// ---------------------------------------------------------------------------
// q-projection GEMM, right-sized: C[m,n] = (sum_k A[m,k]*B[n,k]) + bias[n].
// M=2048, N=256, K=256. 32x32 tiles, BK=32, 256 thr, 2x2 per-thread accums.
// Serial ascending-k fma chain per output + bias after -> numerics identical
// to the previous gemm_nt path. Grid 8x64 = 512 CTAs (vs 32 before).
// ---------------------------------------------------------------------------
__global__ void __launch_bounds__(256) qgemm_kernel(
    const float* __restrict__ A, const float* __restrict__ B,
    float* __restrict__ C, const float* __restrict__ bias)
{
    __shared__ __align__(16) float As[32][33];
    __shared__ __align__(16) float Bs[32][33];

    const int tid = threadIdx.x;
    const int tx  = tid & 15;          // n pair
    const int ty  = tid >> 4;          // m pair
    const int m0  = blockIdx.y * 32;
    const int n0  = blockIdx.x * 32;
    const int lr  = tid >> 3;          // 0..31 tile row
    const int lc  = (tid & 7) * 4;     // k offset (float4)

    float a00 = 0.f, a01 = 0.f, a10 = 0.f, a11 = 0.f;

    for (int k0 = 0; k0 < D_DIM; k0 += 32) {
        float4 va = *(const float4*)(A + (size_t)(m0 + lr) * D_DIM + k0 + lc);
        As[lc + 0][lr] = va.x; As[lc + 1][lr] = va.y;
        As[lc + 2][lr] = va.z; As[lc + 3][lr] = va.w;
        float4 vb = *(const float4*)(B + (size_t)(n0 + lr) * D_DIM + k0 + lc);
        Bs[lc + 0][lr] = vb.x; Bs[lc + 1][lr] = vb.y;
        Bs[lc + 2][lr] = vb.z; Bs[lc + 3][lr] = vb.w;
        __syncthreads();
#pragma unroll
        for (int kk = 0; kk < 32; ++kk) {
            float ra0 = As[kk][ty * 2], ra1 = As[kk][ty * 2 + 1];
            float rb0 = Bs[kk][tx * 2], rb1 = Bs[kk][tx * 2 + 1];
            a00 = fmaf(ra0, rb0, a00);
            a01 = fmaf(ra0, rb1, a01);
            a10 = fmaf(ra1, rb0, a10);
            a11 = fmaf(ra1, rb1, a11);
        }
        __syncthreads();
    }

    int m = m0 + ty * 2, n = n0 + tx * 2;
    float b0 = bias[n], b1 = bias[n + 1];
    C[(size_t)m * D_DIM + n]           = a00 + b0;
    C[(size_t)m * D_DIM + n + 1]       = a01 + b1;
    C[(size_t)(m + 1) * D_DIM + n]     = a10 + b0;
    C[(size_t)(m + 1) * D_DIM + n + 1] = a11 + b1;
}

// ---------------------------------------------------------------------------
// Row L2-normalize + fused bf16 cast. IEEE div/sqrt (matches reference).
// ---------------------------------------------------------------------------
__global__ void l2norm_rows_kernel(const float* __restrict__ src,
                                   float* __restrict__ dstf,
                                   __nv_bfloat16* __restrict__ dstb, int rows)
{
    int row  = blockIdx.x * 8 + (threadIdx.x >> 5);
    int lane = threadIdx.x & 31;
    if (row >= rows) return;
    const float4* p = (const float4*)(src + (size_t)row * D_DIM);
    float4 v0 = p[lane];
    float4 v1 = p[lane + 32];
    float ss = v0.x * v0.x + v0.y * v0.y + v0.z * v0.z + v0.w * v0.w
             + v1.x * v1.x + v1.y * v1.y + v1.z * v1.z + v1.w * v1.w;
#pragma unroll
    for (int off = 16; off > 0; off >>= 1)
        ss += __shfl_xor_sync(0xffffffffu, ss, off);
    float den = fmaxf(__fsqrt_rn(ss), 1e-12f);
    v0.x = __fdiv_rn(v0.x, den); v0.y = __fdiv_rn(v0.y, den);
    v0.z = __fdiv_rn(v0.z, den); v0.w = __fdiv_rn(v0.w, den);
    v1.x = __fdiv_rn(v1.x, den); v1.y = __fdiv_rn(v1.y, den);
    v1.z = __fdiv_rn(v1.z, den); v1.w = __fdiv_rn(v1.w, den);
    float4* q = (float4*)(dstf + (size_t)row * D_DIM);
    q[lane]      = v0;
    q[lane + 32] = v1;
    __nv_bfloat162* d2 = (__nv_bfloat162*)(dstb + (size_t)row * D_DIM);
    d2[lane * 2 + 0]        = __floats2bfloat162_rn(v0.x, v0.y);
    d2[lane * 2 + 1]        = __floats2bfloat162_rn(v0.z, v0.w);
    d2[(lane + 32) * 2 + 0] = __floats2bfloat162_rn(v1.x, v1.y);
    d2[(lane + 32) * 2 + 1] = __floats2bfloat162_rn(v1.z, v1.w);
}

// ---------------------------------------------------------------------------
// Fused candidate + exact rescore + top-8, one block (256 thr) per row.
// ---------------------------------------------------------------------------
__device__ __forceinline__ bool tk_better(float s1, int i1, float s2, int i2)
{
    return (s1 > s2) || (s1 == s2 && i1 < i2);
}

__device__ __forceinline__ float hmax8(uint4 pk)
{
    const __half2* h = (const __half2*)&pk;
    __half2 m01 = __hmax2(h[0], h[1]);
    __half2 m23 = __hmax2(h[2], h[3]);
    __half2 m   = __hmax2(m01, m23);
    return fmaxf(__low2float(m), __high2float(m));
}

__global__ void __launch_bounds__(256) candres_kernel(
    const __half* __restrict__ tmax, const float* __restrict__ q,
    const float* __restrict__ kn,
    float* __restrict__ out_scores, int* __restrict__ topi)
{
    __shared__ __align__(16) float qs[D_DIM];
    __shared__ float st[32][257];          // staged kn rows (conflict-free stride)
    __shared__ float thmax[256];
    __shared__ float sT;
    __shared__ int   scnt;
    __shared__ int   chid[MAXCH];
    __shared__ float cs[MAXCH * 8];
    __shared__ int   ci[MAXCH * 8];
    __shared__ float rs[8];
    __shared__ int   rk[8];
    __shared__ int   rp[8];

    const int r    = blockIdx.x;
    const int tid  = threadIdx.x;
    const int wid  = tid >> 5;
    const int lane = tid & 31;
    const uint4* trow = (const uint4*)(tmax + (size_t)r * N_TCH);

    // q row to smem
    if (tid < 64) ((float4*)qs)[tid] = ((const float4*)(q + (size_t)r * D_DIM))[tid];

    // Pass 1: per-thread slice max over chunk maxes
    float tm = -FLT_MAX;
    for (int g = tid; g < NG8; g += 256)
        tm = fmaxf(tm, hmax8(trow[g]));
    thmax[tid] = tm;
    if (tid == 0) scnt = 0;
    __syncthreads();

    // T = 16th largest of the 256 slice maxes (<= true 16th element value)
    if (tid < 32) {
        float l[8];
#pragma unroll
        for (int j = 0; j < 8; ++j) l[j] = thmax[tid * 8 + j];
        float T = -FLT_MAX;
        for (int it = 0; it < NCAND; ++it) {
            float lm = -FLT_MAX;
#pragma unroll
            for (int j = 0; j < 8; ++j) lm = fmaxf(lm, l[j]);
#pragma unroll
            for (int off = 16; off > 0; off >>= 1)
                lm = fmaxf(lm, __shfl_xor_sync(0xffffffffu, lm, off));
            bool done = false;
#pragma unroll
            for (int j = 0; j < 8; ++j)
                if (!done && l[j] == lm) { l[j] = -FLT_MAX; done = true; }
            T = lm;
        }
        if (tid == 0) sT = T;
    }
    __syncthreads();
    const float T = sT;

    // Pass 2: collect hot chunk ids (row cache-hot, ~25 hits)
    for (int g = tid; g < NG8; g += 256) {
        uint4 pk = trow[g];
        if (hmax8(pk) >= T) {
            const __half2* h = (const __half2*)&pk;
#pragma unroll
            for (int v = 0; v < 4; ++v) {
                float2 f = __half22float2(h[v]);
                if (f.x >= T) { int p = atomicAdd(&scnt, 1); if (p < MAXCH) chid[p] = g * 8 + v * 2; }
                if (f.y >= T) { int p = atomicAdd(&scnt, 1); if (p < MAXCH) chid[p] = g * 8 + v * 2 + 1; }
            }
        }
    }
    __syncthreads();
    const int CE = min(scnt, MAXCH) * 8;

    // Tiled exact rescore: stage 32 candidate rows coalesced, then serial
    // ascending-k fma chain from smem (identical numerics to prior rounds).
    for (int t0 = 0; t0 < CE; t0 += 32) {
        const int nr = min(32, CE - t0);
#pragma unroll
        for (int j = 0; j < 8; ++j) {
            int u  = j * 256 + tid;
            int lr = u >> 6;
            int lc = u & 63;
            if (lr < nr) {
                int e = t0 + lr;
                int n = chid[e >> 3] * 8 + (e & 7);
                float4 v = ((const float4*)(kn + (size_t)n * D_DIM))[lc];
                st[lr][lc * 4 + 0] = v.x; st[lr][lc * 4 + 1] = v.y;
                st[lr][lc * 4 + 2] = v.z; st[lr][lc * 4 + 3] = v.w;
            }
        }
        __syncthreads();
        if (tid < nr) {
            int e = t0 + tid;
            int n = chid[e >> 3] * 8 + (e & 7);
            float acc = 0.f;
#pragma unroll 8
            for (int k = 0; k < D_DIM; ++k)
                acc = fmaf(qs[k], st[tid][k], acc);
            cs[e] = acc; ci[e] = n;
        }
        __syncthreads();
    }

    // Exact (score, index) top-8 via warp-shuffle reductions (2 barriers/iter)
    for (int it = 0; it < TOPK; ++it) {
        float bs = -FLT_MAX; int bk = 0x7fffffff; int bp = -1;
        for (int i = tid; i < CE; i += 256)
            if (tk_better(cs[i], ci[i], bs, bk)) { bs = cs[i]; bk = ci[i]; bp = i; }
#pragma unroll
        for (int off = 16; off > 0; off >>= 1) {
            float os = __shfl_down_sync(0xffffffffu, bs, off);
            int   ok = __shfl_down_sync(0xffffffffu, bk, off);
            int   op = __shfl_down_sync(0xffffffffu, bp, off);
            if (tk_better(os, ok, bs, bk)) { bs = os; bk = ok; bp = op; }
        }
        if (lane == 0) { rs[wid] = bs; rk[wid] = bk; rp[wid] = bp; }
        __syncthreads();
        if (tid < 8) {
            bs = rs[tid]; bk = rk[tid]; bp = rp[tid];
#pragma unroll
            for (int off = 4; off > 0; off >>= 1) {
                float os = __shfl_down_sync(0x000000ffu, bs, off, 8);
                int   ok = __shfl_down_sync(0x000000ffu, bk, off, 8);
                int   op = __shfl_down_sync(0x000000ffu, bp, off, 8);
                if (tk_better(os, ok, bs, bk)) { bs = os; bk = ok; bp = op; }
            }
            if (tid == 0) {
                out_scores[r * TOPK + it] = bs;
                topi[r * TOPK + it]       = bk;
                if (bp >= 0) { cs[bp] = -FLT_MAX; ci[bp] = 0x7fffffff; }
            }
        }
        __syncthreads();
    }
}

// ---------------------------------------------------------------------------
// usage passthrough + gather
// ---------------------------------------------------------------------------
__global__ void usage_init_kernel(const float* __restrict__ usage, float* __restrict__ out_usage)
{
    int i = blockIdx.x * blockDim.x + threadIdx.x;
    if (i < N_KEYS) out_usage[i] = usage[i];
}

__global__ void gather_kernel(const float* __restrict__ values, const int* __restrict__ topi,
                              float* __restrict__ out_rv, float* __restrict__ out_usage)
{
    int slot = blockIdx.x;
    int idx  = topi[slot];
    if (threadIdx.x == 0) atomicAdd(&out_usage[idx], 1.0f);
    const float4* src = (const float4*)(values + (size_t)idx * V_DIM);
    float4*       dst = (float4*)(out_rv + (size_t)slot * V_DIM);
    dst[threadIdx.x] = src[threadIdx.x];
}

// ---------------------------------------------------------------------------
// Launch
// ---------------------------------------------------------------------------
extern "C" void kernel_launch(void* const* d_in, const int* in_sizes, int n_in,
                              void* d_out, int out_size)
{
    const float* query  = (const float*)d_in[0];
    const float* W      = (const float*)d_in[1];
    const float* bias   = (const float*)d_in[2];
    const float* keys   = (const float*)d_in[3];
    const float* values = (const float*)d_in[4];
    const float* usage  = (const float*)d_in[5];

    float* out       = (float*)d_out;
    float* out_rv    = out;
    float* out_sc    = out + (size_t)B_ROWS * TOPK * V_DIM;
    float* out_usage = out_sc + (size_t)B_ROWS * TOPK;

    float*         q    = nullptr; cudaGetSymbolAddress((void**)&q,    g_q);
    float*         kn   = nullptr; cudaGetSymbolAddress((void**)&kn,   g_kn);
    __nv_bfloat16* ah   = nullptr; cudaGetSymbolAddress((void**)&ah,   g_ah);
    __nv_bfloat16* bh   = nullptr; cudaGetSymbolAddress((void**)&bh,   g_bh);
    __half*        tmx  = nullptr; cudaGetSymbolAddress((void**)&tmx,  g_tmax);
    int*           topi = nullptr; cudaGetSymbolAddress((void**)&topi, g_topi);

    // 1) q = query @ W^T + b   (right-sized: 512 CTAs)
    qgemm_kernel<<<dim3(D_DIM / 32, B_ROWS / 32), 256>>>(query, W, q, bias);

    // 2) normalize + fused bf16 cast; zero bh pad rows
    l2norm_rows_kernel<<<B_ROWS / 8, 256>>>(q, q, ah, B_ROWS);
    l2norm_rows_kernel<<<(N_KEYS + 7) / 8, 256>>>(keys, kn, bh, N_KEYS);
    cudaMemsetAsync(bh + (size_t)N_KEYS * D_DIM, 0,
                    (size_t)(N_PAD - N_KEYS) * D_DIM * sizeof(__nv_bfloat16));

    // 3) bf16 tensor-core GEMM -> chunk maxes only (no sim matrix)
    simtc_kernel<<<dim3(N_PAD / 128, B_ROWS / 128), 256>>>(ah, bh, tmx);

    // 4) fused threshold + collect + coalesced exact rescore + top-8
    candres_kernel<<<B_ROWS, 256>>>(tmx, q, kn, out_sc, topi);

    // 5) usage + gather
    usage_init_kernel<<<(N_KEYS + 255) / 256, 256>>>(usage, out_usage);
    gather_kernel<<<B_ROWS * TOPK, 64>>>(values, topi, out_rv, out_usage);
}